// round 7
// baseline (speedup 1.0000x reference)
#include <cuda_runtime.h>
#include <cuda_bf16.h>
#include <math.h>
#include <string.h>
#include <stdint.h>

#define NB    8
#define LSEQ  2048
#define MTOK  (NB*LSEQ)     // 16384 tokens
#define DIN   64
#define DOUT  64
#define DM    512
#define DS    256
#define NL    4
#define NCH   16
#define CHLEN (LSEQ/NCH)    // 128

// ---------------- scratch (device globals; no allocation allowed) ----------------
__device__ float g_x [MTOK*DM];
__device__ float g_bu[MTOK*DM];           // Bu packed [re(256) | im(256)]
__device__ float g_h [MTOK*DM];           // h  packed [re | im]
__device__ float g_z [MTOK*DM];           // LRU output
// pre-split weights (bf16 hi/lo)
__device__ __nv_bfloat16 g_Wbhi[NL*DM*DM],   g_Wblo[NL*DM*DM];
__device__ __nv_bfloat16 g_Wchi[NL*DM*DM],   g_Wclo[NL*DM*DM];
__device__ __nv_bfloat16 g_Wghi[NL*2*DM*DM], g_Wglo[NL*2*DM*DM];
__device__ __nv_bfloat16 g_enchi[DM*DIN],    g_enclo[DM*DIN];
__device__ __nv_bfloat16 g_dechi[128*DM],    g_declo[128*DM];   // padded to 128 rows
// scan params / carries
__device__ float g_lre[NL*DS], g_lim[NL*DS], g_gam[NL*DS], g_sres[NL];
__device__ float g_cend[NB*NCH*2*DS], g_cin[NB*NCH*2*DS];

// ---------------- helpers ----------------
__device__ __forceinline__ uint32_t smem_u32(const void* p) {
    uint32_t a;
    asm("{ .reg .u64 t; cvta.to.shared.u64 t, %1; cvt.u32.u64 %0, t; }" : "=r"(a) : "l"(p));
    return a;
}
__device__ __forceinline__ uint32_t sw128(uint32_t b) { return b ^ ((b >> 3) & 0x70); }

__device__ __forceinline__ void ldsm4(uint32_t* r, uint32_t addr) {
    asm volatile("ldmatrix.sync.aligned.m8n8.x4.shared.b16 {%0,%1,%2,%3}, [%4];"
                 : "=r"(r[0]), "=r"(r[1]), "=r"(r[2]), "=r"(r[3]) : "r"(addr));
}
__device__ __forceinline__ void mma_bf16(float* c, const uint32_t* a, const uint32_t* b) {
    asm volatile(
        "mma.sync.aligned.m16n8k16.row.col.f32.bf16.bf16.f32 "
        "{%0,%1,%2,%3}, {%4,%5,%6,%7}, {%8,%9}, {%0,%1,%2,%3};"
        : "+f"(c[0]), "+f"(c[1]), "+f"(c[2]), "+f"(c[3])
        : "r"(a[0]), "r"(a[1]), "r"(a[2]), "r"(a[3]), "r"(b[0]), "r"(b[1]));
}

struct Pack8 { uint4 hi, lo; };

__device__ __forceinline__ uint32_t pk(float a, float b) {
    __nv_bfloat162 t = __floats2bfloat162_rn(a, b);
    uint32_t u; memcpy(&u, &t, 4); return u;
}

// load 8 fp32, split into bf16 hi (16B) + lo (16B)
__device__ __forceinline__ Pack8 load_split(const float* p) {
    Pack8 o;
    float4 v0 = *reinterpret_cast<const float4*>(p);
    float4 v1 = *reinterpret_cast<const float4*>(p + 4);
    o.hi.x = pk(v0.x, v0.y); o.hi.y = pk(v0.z, v0.w);
    o.hi.z = pk(v1.x, v1.y); o.hi.w = pk(v1.z, v1.w);
    __nv_bfloat162 h;
    float r[8];
    memcpy(&h, &o.hi.x, 4); r[0] = v0.x - __bfloat162float(h.x); r[1] = v0.y - __bfloat162float(h.y);
    memcpy(&h, &o.hi.y, 4); r[2] = v0.z - __bfloat162float(h.x); r[3] = v0.w - __bfloat162float(h.y);
    memcpy(&h, &o.hi.z, 4); r[4] = v1.x - __bfloat162float(h.x); r[5] = v1.y - __bfloat162float(h.y);
    memcpy(&h, &o.hi.w, 4); r[6] = v1.z - __bfloat162float(h.x); r[7] = v1.w - __bfloat162float(h.y);
    o.lo.x = pk(r[0], r[1]); o.lo.y = pk(r[2], r[3]);
    o.lo.z = pk(r[4], r[5]); o.lo.w = pk(r[6], r[7]);
    return o;
}

__device__ __forceinline__ void split1(float v, __nv_bfloat16* h, __nv_bfloat16* l) {
    __nv_bfloat16 hh = __float2bfloat16(v);
    *h = hh;
    *l = __float2bfloat16(v - __bfloat162float(hh));
}

// ---------------- prep kernels (merged: exactly 4 launches before GEMMs) ------
__global__ void prep_lam_kernel(const float* __restrict__ nu_log,
                                const float* __restrict__ th_log,
                                const float* __restrict__ rlog) {
    int i = blockIdx.x * blockDim.x + threadIdx.x;
    if (i < NL*DS) {
        float nu = expf(nu_log[i]);
        float r  = expf(-nu);
        float th = expf(th_log[i]);
        g_lre[i] = r * cosf(th);
        g_lim[i] = r * sinf(th);
        g_gam[i] = sqrtf(fmaxf(1.0f - r*r, 0.0f));
    }
    if (i < NL) g_sres[i] = 1.0f / (1.0f + expf(-rlog[i]));
}

__global__ void prep_wb_enc_kernel(const float* __restrict__ Bre, const float* __restrict__ Bim,
                                   const float* __restrict__ enc_w) {
    int idx = blockIdx.x * blockDim.x + threadIdx.x;
    if (idx < NL*DM*DM) {
        int l = idx / (DM*DM), rem = idx - l*(DM*DM);
        int n = rem / DM, k = rem - n*DM;
        float v;
        if (n < DS) v = g_gam[l*DS + n]      * Bre[((size_t)l*DS + n)*DM + k];
        else        v = g_gam[l*DS + n - DS] * Bim[((size_t)l*DS + (n-DS))*DM + k];
        split1(v, &g_Wbhi[idx], &g_Wblo[idx]);
    } else {
        int e = idx - NL*DM*DM;
        if (e < DM*DIN) split1(enc_w[e], &g_enchi[e], &g_enclo[e]);
    }
}

__global__ void prep_wc_dec_kernel(const float* __restrict__ Cre, const float* __restrict__ Cim,
                                   const float* __restrict__ dec_w) {
    int idx = blockIdx.x * blockDim.x + threadIdx.x;
    if (idx < NL*DM*DM) {
        int l = idx / (DM*DM), rem = idx - l*(DM*DM);
        int d = rem / DM, k = rem - d*DM;
        float v;
        if (k < DS) v =  Cre[((size_t)l*DM + d)*DS + k];
        else        v = -Cim[((size_t)l*DM + d)*DS + (k-DS)];
        split1(v, &g_Wchi[idx], &g_Wclo[idx]);
    } else {
        int e = idx - NL*DM*DM;
        if (e < 128*DM) {
            int row = e / DM;
            float v = (row < DOUT) ? dec_w[e] : 0.0f;
            split1(v, &g_dechi[e], &g_declo[e]);
        }
    }
}

__global__ void prep_wglu_kernel(const float* __restrict__ W1, const float* __restrict__ W2) {
    int idx = blockIdx.x * blockDim.x + threadIdx.x;
    if (idx >= NL*2*DM*DM) return;
    int l = idx / (2*DM*DM), rem = idx - l*(2*DM*DM);
    int n = rem / DM, k = rem - n*DM;
    int o = n >> 1;
    float v = (n & 1) ? W2[((size_t)l*DM + o)*DM + k]
                      : W1[((size_t)l*DM + o)*DM + k];
    split1(v, &g_Wghi[idx], &g_Wglo[idx]);
}

// ---------------- HMMA GEMM: BK=64, single-sync double buffer ----------------
// A: fp32 (split inline). W: pre-split bf16 hi/lo.
// SMEM per stage (64KB): [A_hi 16K][A_lo 16K][W_hi 16K][W_lo 16K], rows of 128B (64 bf16).
// EPI: 0 plain, 1 += Dvec[n]*Xres[m,n], 2 GLU: Xout[m,n/2] += s*even*sigmoid(odd)
#define STAGEB 65536

template<int EPI, bool WGUARD>
__global__ __launch_bounds__(256, 1)
void hmma_gemm(const float* __restrict__ A,
               const __nv_bfloat16* __restrict__ Whi, const __nv_bfloat16* __restrict__ Wlo,
               float* __restrict__ C, int K, int Ntot,
               const float* __restrict__ Dvec, const float* __restrict__ Xres,
               const float* __restrict__ sres_p, float* __restrict__ Xout) {
    extern __shared__ char smem[];
    const int tid  = threadIdx.x;
    const int wid  = tid >> 5;
    const int lane = tid & 31;
    const int wm   = wid & 1;      // M half (64 rows)
    const int wn   = wid >> 1;     // N quarter (32 cols)
    const int bm   = blockIdx.y * 128;
    const int bn   = blockIdx.x * 128;

    float acc[4][4][4];
#pragma unroll
    for (int i = 0; i < 4; i++)
#pragma unroll
        for (int j = 0; j < 4; j++)
#pragma unroll
            for (int q = 0; q < 4; q++) acc[i][j][q] = 0.0f;

    const int NK = K >> 6;   // chunks of 64
    // fill mapping: thread -> row (tid>>1, 0..127) and half (tid&1)
    const int frow  = tid >> 1;
    const int fhalf = tid & 1;

    Pack8 pa[4];      // A stage: 4 x 8 floats (row frow, cols fhalf*32 + q*8)
    uint4 pw[8];      // W stage: 128 bytes (row frow, half fhalf selects hi/lo)

    // ---- stage chunk 0 ----
    {
        const float* ap = A + (size_t)(bm + frow)*K + fhalf*32;
#pragma unroll
        for (int q = 0; q < 4; q++) pa[q] = load_split(ap + q*8);
        const uint4* wp = reinterpret_cast<const uint4*>(
            (fhalf ? Wlo : Whi) + (size_t)(bn + frow)*K);
#pragma unroll
        for (int q = 0; q < 8; q++) pw[q] = wp[q];
    }
    // ---- store chunk 0 -> buf 0 ----
    {
        char* s = smem;
        const uint32_t arow = (uint32_t)(frow*128 + fhalf*64);
#pragma unroll
        for (int q = 0; q < 4; q++) {
            *reinterpret_cast<uint4*>(s +          sw128(arow + q*16)) = pa[q].hi;
            *reinterpret_cast<uint4*>(s + 16384 +  sw128(arow + q*16)) = pa[q].lo;
        }
        char* w = s + 32768 + fhalf*16384;
        const uint32_t wrow = (uint32_t)(frow*128);
#pragma unroll
        for (int q = 0; q < 8; q++)
            *reinterpret_cast<uint4*>(w + sw128(wrow + q*16)) = pw[q];
    }

    // per-lane ldmatrix address components
    const int a_row = wm*64 + (lane & 7) + ((lane >> 3) & 1)*8;
    const int a_kb  = (lane >> 4) << 4;
    const int b_sub = lane >> 3;
    const int b_row = wn*32 + (lane & 7) + (b_sub >> 1)*8;
    const int b_kb  = (b_sub & 1) << 4;

    for (int t = 0; t < NK; ++t) {
        if (t + 1 < NK) {   // stage next chunk (long-latency LDG ahead of barrier)
            const int k0 = (t + 1) << 6;
            const float* ap = A + (size_t)(bm + frow)*K + k0 + fhalf*32;
#pragma unroll
            for (int q = 0; q < 4; q++) pa[q] = load_split(ap + q*8);
            const uint4* wp = reinterpret_cast<const uint4*>(
                (fhalf ? Wlo : Whi) + (size_t)(bn + frow)*K + k0);
#pragma unroll
            for (int q = 0; q < 8; q++) pw[q] = wp[q];
        }
        __syncthreads();    // buf[t&1] fully stored; previous readers done
        const uint32_t As = smem_u32(smem + (t & 1)*STAGEB);
        const uint32_t Ws = As + 32768;
#pragma unroll
        for (int s = 0; s < 4; ++s) {   // 4 x K=16
            uint32_t ahi[4][4], alo[4][4], bhi[4][2], blo[4][2];
#pragma unroll
            for (int i = 0; i < 4; i++) {
                uint32_t base = (uint32_t)((a_row + 16*i)*128 + s*32 + a_kb);
                ldsm4(ahi[i], As +          sw128(base));
                ldsm4(alo[i], As + 16384 +  sw128(base));
            }
#pragma unroll
            for (int jj = 0; jj < 2; jj++) {
                uint32_t base = (uint32_t)((b_row + 16*jj)*128 + s*32 + b_kb);
                uint32_t r[4];
                ldsm4(r, Ws + sw128(base));
                bhi[2*jj][0] = r[0]; bhi[2*jj][1] = r[1];
                bhi[2*jj+1][0] = r[2]; bhi[2*jj+1][1] = r[3];
                ldsm4(r, Ws + 16384 + sw128(base));
                blo[2*jj][0] = r[0]; blo[2*jj][1] = r[1];
                blo[2*jj+1][0] = r[2]; blo[2*jj+1][1] = r[3];
            }
#pragma unroll
            for (int i = 0; i < 4; i++)
#pragma unroll
                for (int j = 0; j < 4; j++) {
                    mma_bf16(acc[i][j], ahi[i], bhi[j]);
                    mma_bf16(acc[i][j], ahi[i], blo[j]);
                    mma_bf16(acc[i][j], alo[i], bhi[j]);
                }
        }
        if (t + 1 < NK) {   // store staged chunk into the other buffer
            char* s = smem + ((t + 1) & 1)*STAGEB;
            const uint32_t arow = (uint32_t)(frow*128 + fhalf*64);
#pragma unroll
            for (int q = 0; q < 4; q++) {
                *reinterpret_cast<uint4*>(s +         sw128(arow + q*16)) = pa[q].hi;
                *reinterpret_cast<uint4*>(s + 16384 + sw128(arow + q*16)) = pa[q].lo;
            }
            char* w = s + 32768 + fhalf*16384;
            const uint32_t wrow = (uint32_t)(frow*128);
#pragma unroll
            for (int q = 0; q < 8; q++)
                *reinterpret_cast<uint4*>(w + sw128(wrow + q*16)) = pw[q];
        }
    }

    // epilogue
    const int gid = lane >> 2;
    const int tg  = lane & 3;
#pragma unroll
    for (int i = 0; i < 4; i++) {
        const int r0 = bm + wm*64 + i*16 + gid;
#pragma unroll
        for (int j = 0; j < 4; j++) {
            const int col = bn + wn*32 + j*8 + tg*2;
            if (EPI == 2) {
                const float s = *sres_p;
                const int oc = col >> 1;
                float* xp0 = Xout + (size_t)r0 * DM + oc;
                float* xp1 = Xout + (size_t)(r0+8) * DM + oc;
                *xp0 = fmaf(s * acc[i][j][0], 1.0f/(1.0f + expf(-acc[i][j][1])), *xp0);
                *xp1 = fmaf(s * acc[i][j][2], 1.0f/(1.0f + expf(-acc[i][j][3])), *xp1);
            } else {
                if (WGUARD && col >= Ntot) continue;
                float2 v0 = make_float2(acc[i][j][0], acc[i][j][1]);
                float2 v1 = make_float2(acc[i][j][2], acc[i][j][3]);
                if (EPI == 1) {
                    const float2 d  = *reinterpret_cast<const float2*>(Dvec + col);
                    const float2 x0 = *reinterpret_cast<const float2*>(Xres + (size_t)r0*Ntot + col);
                    const float2 x1 = *reinterpret_cast<const float2*>(Xres + (size_t)(r0+8)*Ntot + col);
                    v0.x = fmaf(d.x, x0.x, v0.x); v0.y = fmaf(d.y, x0.y, v0.y);
                    v1.x = fmaf(d.x, x1.x, v1.x); v1.y = fmaf(d.y, x1.y, v1.y);
                }
                *reinterpret_cast<float2*>(C + (size_t)r0*Ntot + col)     = v0;
                *reinterpret_cast<float2*>(C + (size_t)(r0+8)*Ntot + col) = v1;
            }
        }
    }
}

// ---------------- chunked LRU scan ----------------
__global__ void scan_local_kernel(const float* __restrict__ Bu, float* __restrict__ H,
                                  const float* __restrict__ lre_g,
                                  const float* __restrict__ lim_g) {
    int n = threadIdx.x;
    int b = blockIdx.x;
    int c = blockIdx.y;
    float lre = lre_g[n], lim = lim_g[n];
    size_t base = ((size_t)b * LSEQ + (size_t)c * CHLEN) * DM + n;
    float hre = 0.0f, him = 0.0f;
#pragma unroll 4
    for (int t = 0; t < CHLEN; ++t) {
        size_t off = base + (size_t)t * DM;
        float bre = Bu[off];
        float bim = Bu[off + DS];
        float nre = fmaf(lre, hre, fmaf(-lim, him, bre));
        float nim = fmaf(lim, hre, fmaf( lre, him, bim));
        hre = nre; him = nim;
        H[off]      = hre;
        H[off + DS] = him;
    }
    int ci = b * NCH + c;
    g_cend[(size_t)ci*2*DS + n]      = hre;
    g_cend[(size_t)ci*2*DS + DS + n] = him;
}

__global__ void scan_carry_kernel(const float* __restrict__ lre_g,
                                  const float* __restrict__ lim_g) {
    int n = threadIdx.x;
    int b = blockIdx.x;
    float lre = lre_g[n], lim = lim_g[n];
    float pre = lre, pim = lim;
#pragma unroll
    for (int i = 0; i < 7; i++) {     // lam^128
        float t = pre*pre - pim*pim;
        pim = 2.0f*pre*pim;
        pre = t;
    }
    float sre = 0.0f, sim = 0.0f;
    for (int c = 0; c < NCH; ++c) {
        size_t ci = (size_t)(b * NCH + c) * 2 * DS;
        g_cin[ci + n]      = sre;
        g_cin[ci + DS + n] = sim;
        float ere = g_cend[ci + n];
        float eim = g_cend[ci + DS + n];
        float nre = fmaf(pre, sre, fmaf(-pim, sim, ere));
        float nim = fmaf(pim, sre, fmaf( pre, sim, eim));
        sre = nre; sim = nim;
    }
}

__global__ void scan_fix_kernel(float* __restrict__ H,
                                const float* __restrict__ lre_g,
                                const float* __restrict__ lim_g) {
    int n = threadIdx.x;
    int b = blockIdx.x;
    int c = blockIdx.y + 1;
    float lre = lre_g[n], lim = lim_g[n];
    size_t ci = (size_t)(b * NCH + c) * 2 * DS;
    float cre = g_cin[ci + n];
    float cim = g_cin[ci + DS + n];
    float pre = lre, pim = lim;
    size_t base = ((size_t)b * LSEQ + (size_t)c * CHLEN) * DM + n;
#pragma unroll 4
    for (int t = 0; t < CHLEN; ++t) {
        size_t off = base + (size_t)t * DM;
        float hre = H[off]      + (pre*cre - pim*cim);
        float him = H[off + DS] + (pre*cim + pim*cre);
        H[off]      = hre;
        H[off + DS] = him;
        float npre = pre*lre - pim*lim;
        float npim = pre*lim + pim*lre;
        pre = npre; pim = npim;
    }
}

// ---------------- host launch ----------------
extern "C" void kernel_launch(void* const* d_in, const int* in_sizes, int n_in,
                              void* d_out, int out_size) {
    const float* u      = (const float*)d_in[0];
    const float* enc_w  = (const float*)d_in[1];
    const float* dec_w  = (const float*)d_in[2];
    const float* nu_log = (const float*)d_in[3];
    const float* th_log = (const float*)d_in[4];
    const float* Bre    = (const float*)d_in[5];
    const float* Bim    = (const float*)d_in[6];
    const float* Cre    = (const float*)d_in[7];
    const float* Cim    = (const float*)d_in[8];
    const float* Dv     = (const float*)d_in[9];
    const float* W1     = (const float*)d_in[10];
    const float* W2     = (const float*)d_in[11];
    const float* rlog   = (const float*)d_in[12];
    float* out = (float*)d_out;

    float *px, *pbu, *ph, *pz, *plre, *plim, *psres;
    __nv_bfloat16 *pWbhi, *pWblo, *pWchi, *pWclo, *pWghi, *pWglo;
    __nv_bfloat16 *penchi, *penclo, *pdechi, *pdeclo;
    cudaGetSymbolAddress((void**)&px,   g_x);
    cudaGetSymbolAddress((void**)&pbu,  g_bu);
    cudaGetSymbolAddress((void**)&ph,   g_h);
    cudaGetSymbolAddress((void**)&pz,   g_z);
    cudaGetSymbolAddress((void**)&pWbhi, g_Wbhi); cudaGetSymbolAddress((void**)&pWblo, g_Wblo);
    cudaGetSymbolAddress((void**)&pWchi, g_Wchi); cudaGetSymbolAddress((void**)&pWclo, g_Wclo);
    cudaGetSymbolAddress((void**)&pWghi, g_Wghi); cudaGetSymbolAddress((void**)&pWglo, g_Wglo);
    cudaGetSymbolAddress((void**)&penchi, g_enchi); cudaGetSymbolAddress((void**)&penclo, g_enclo);
    cudaGetSymbolAddress((void**)&pdechi, g_dechi); cudaGetSymbolAddress((void**)&pdeclo, g_declo);
    cudaGetSymbolAddress((void**)&plre,  g_lre);
    cudaGetSymbolAddress((void**)&plim,  g_lim);
    cudaGetSymbolAddress((void**)&psres, g_sres);

    const int SMEM = 2 * STAGEB;   // 128 KB
    cudaFuncSetAttribute(hmma_gemm<0,false>, cudaFuncAttributeMaxDynamicSharedMemorySize, SMEM);
    cudaFuncSetAttribute(hmma_gemm<1,false>, cudaFuncAttributeMaxDynamicSharedMemorySize, SMEM);
    cudaFuncSetAttribute(hmma_gemm<2,false>, cudaFuncAttributeMaxDynamicSharedMemorySize, SMEM);
    cudaFuncSetAttribute(hmma_gemm<0,true>,  cudaFuncAttributeMaxDynamicSharedMemorySize, SMEM);

    // prep: exactly 4 launches so launch index 5 = first Bu GEMM (ncu -s 5 -c 1)
    prep_lam_kernel   <<<(NL*DS + 255)/256, 256>>>(nu_log, th_log, rlog);
    prep_wb_enc_kernel<<<(NL*DM*DM + DM*DIN + 255)/256, 256>>>(Bre, Bim, enc_w);
    prep_wc_dec_kernel<<<(NL*DM*DM + 128*DM + 255)/256, 256>>>(Cre, Cim, dec_w);
    prep_wglu_kernel  <<<(NL*2*DM*DM + 255)/256, 256>>>(W1, W2);

    // launch #4: encoder (K=64 -> NK=1)
    hmma_gemm<0,false><<<dim3(DM/128, MTOK/128), 256, SMEM>>>(
        u, penchi, penclo, px, DIN, DM, nullptr, nullptr, nullptr, nullptr);

    for (int l = 0; l < NL; ++l) {
        const float* lre = plre + l*DS;
        const float* lim = plim + l*DS;
        // launch #5 (l=0): Bu = x @ Wb^T
        hmma_gemm<0,false><<<dim3(DM/128, MTOK/128), 256, SMEM>>>(
            px, pWbhi + (size_t)l*DM*DM, pWblo + (size_t)l*DM*DM,
            pbu, DM, DM, nullptr, nullptr, nullptr, nullptr);
        scan_local_kernel<<<dim3(NB, NCH), DS>>>(pbu, ph, lre, lim);
        scan_carry_kernel<<<NB, DS>>>(lre, lim);
        scan_fix_kernel<<<dim3(NB, NCH-1), DS>>>(ph, lre, lim);
        // z = Re(C h) + D*x
        hmma_gemm<1,false><<<dim3(DM/128, MTOK/128), 256, SMEM>>>(
            ph, pWchi + (size_t)l*DM*DM, pWclo + (size_t)l*DM*DM,
            pz, DM, DM, Dv + l*DM, px, nullptr, nullptr);
        // GLU GEMM (N=1024 interleaved): x += s*g1*sigmoid(g2)
        hmma_gemm<2,false><<<dim3(2*DM/128, MTOK/128), 256, SMEM>>>(
            pz, pWghi + (size_t)l*2*DM*DM, pWglo + (size_t)l*2*DM*DM,
            nullptr, DM, 2*DM, nullptr, nullptr, psres + l, px);
    }

    // decoder: out = x @ dec_w^T (N=64 guarded; weights padded to 128 rows)
    hmma_gemm<0,true><<<dim3(1, MTOK/128), 256, SMEM>>>(
        px, pdechi, pdeclo, out, DM, DOUT, nullptr, nullptr, nullptr, nullptr);
}

// round 8
// speedup vs baseline: 1.4350x; 1.4350x over previous
#include <cuda_runtime.h>
#include <cuda_bf16.h>
#include <math.h>
#include <string.h>
#include <stdint.h>

#define NB    8
#define LSEQ  2048
#define MTOK  (NB*LSEQ)     // 16384 tokens
#define DIN   64
#define DOUT  64
#define DM    512
#define DS    256
#define NL    4
#define NCH   16
#define CHLEN (LSEQ/NCH)    // 128

// ---------------- scratch (device globals; no allocation allowed) ----------------
__device__ float g_x [MTOK*DM];
__device__ float g_bu[MTOK*DM];           // Bu packed [re(256) | im(256)]
__device__ float g_h [MTOK*DM];           // h  packed [re | im]
__device__ float g_z [MTOK*DM];           // LRU output
// pre-split weights (bf16 hi/lo)
__device__ __nv_bfloat16 g_Wbhi[NL*DM*DM],   g_Wblo[NL*DM*DM];
__device__ __nv_bfloat16 g_Wchi[NL*DM*DM],   g_Wclo[NL*DM*DM];
__device__ __nv_bfloat16 g_Wghi[NL*2*DM*DM], g_Wglo[NL*2*DM*DM];
__device__ __nv_bfloat16 g_enchi[DM*DIN],    g_enclo[DM*DIN];
__device__ __nv_bfloat16 g_dechi[128*DM],    g_declo[128*DM];   // padded to 128 rows
// scan params / carries
__device__ float g_lre[NL*DS], g_lim[NL*DS], g_gam[NL*DS], g_sres[NL];
__device__ float g_cend[NB*NCH*2*DS], g_cin[NB*NCH*2*DS];

// ---------------- helpers ----------------
__device__ __forceinline__ uint32_t smem_u32(const void* p) {
    uint32_t a;
    asm("{ .reg .u64 t; cvta.to.shared.u64 t, %1; cvt.u32.u64 %0, t; }" : "=r"(a) : "l"(p));
    return a;
}
__device__ __forceinline__ uint32_t sw128(uint32_t b) { return b ^ ((b >> 3) & 0x70); }

__device__ __forceinline__ void ldsm4(uint32_t* r, uint32_t addr) {
    asm volatile("ldmatrix.sync.aligned.m8n8.x4.shared.b16 {%0,%1,%2,%3}, [%4];"
                 : "=r"(r[0]), "=r"(r[1]), "=r"(r[2]), "=r"(r[3]) : "r"(addr));
}
__device__ __forceinline__ void mma_bf16(float* c, const uint32_t* a, const uint32_t* b) {
    asm volatile(
        "mma.sync.aligned.m16n8k16.row.col.f32.bf16.bf16.f32 "
        "{%0,%1,%2,%3}, {%4,%5,%6,%7}, {%8,%9}, {%0,%1,%2,%3};"
        : "+f"(c[0]), "+f"(c[1]), "+f"(c[2]), "+f"(c[3])
        : "r"(a[0]), "r"(a[1]), "r"(a[2]), "r"(a[3]), "r"(b[0]), "r"(b[1]));
}
__device__ __forceinline__ void cpasync16(uint32_t d, const void* s) {
    asm volatile("cp.async.cg.shared.global [%0], [%1], 16;" :: "r"(d), "l"(s));
}
__device__ __forceinline__ void cp_commit() { asm volatile("cp.async.commit_group;" ::: "memory"); }
template<int N> __device__ __forceinline__ void cp_wait() {
    asm volatile("cp.async.wait_group %0;" :: "n"(N) : "memory");
}

struct Pack8 { uint4 hi, lo; };

__device__ __forceinline__ uint32_t pk(float a, float b) {
    __nv_bfloat162 t = __floats2bfloat162_rn(a, b);
    uint32_t u; memcpy(&u, &t, 4); return u;
}

// load 8 fp32, split into bf16 hi (16B) + lo (16B)
__device__ __forceinline__ Pack8 load_split(const float* p) {
    Pack8 o;
    float4 v0 = *reinterpret_cast<const float4*>(p);
    float4 v1 = *reinterpret_cast<const float4*>(p + 4);
    o.hi.x = pk(v0.x, v0.y); o.hi.y = pk(v0.z, v0.w);
    o.hi.z = pk(v1.x, v1.y); o.hi.w = pk(v1.z, v1.w);
    __nv_bfloat162 h;
    float r[8];
    memcpy(&h, &o.hi.x, 4); r[0] = v0.x - __bfloat162float(h.x); r[1] = v0.y - __bfloat162float(h.y);
    memcpy(&h, &o.hi.y, 4); r[2] = v0.z - __bfloat162float(h.x); r[3] = v0.w - __bfloat162float(h.y);
    memcpy(&h, &o.hi.z, 4); r[4] = v1.x - __bfloat162float(h.x); r[5] = v1.y - __bfloat162float(h.y);
    memcpy(&h, &o.hi.w, 4); r[6] = v1.z - __bfloat162float(h.x); r[7] = v1.w - __bfloat162float(h.y);
    o.lo.x = pk(r[0], r[1]); o.lo.y = pk(r[2], r[3]);
    o.lo.z = pk(r[4], r[5]); o.lo.w = pk(r[6], r[7]);
    return o;
}

__device__ __forceinline__ void store_pair(char* base, int row, int q, const Pack8& p8) {
    *reinterpret_cast<uint4*>(base + sw128((uint32_t)(row*128 + q*16)))      = p8.hi;
    *reinterpret_cast<uint4*>(base + sw128((uint32_t)(row*128 + 64 + q*16))) = p8.lo;
}

__device__ __forceinline__ void split1(float v, __nv_bfloat16* h, __nv_bfloat16* l) {
    __nv_bfloat16 hh = __float2bfloat16(v);
    *h = hh;
    *l = __float2bfloat16(v - __bfloat162float(hh));
}

// ---------------- prep kernels (merged) ----------------
__global__ void prep_lam_kernel(const float* __restrict__ nu_log,
                                const float* __restrict__ th_log,
                                const float* __restrict__ rlog) {
    int i = blockIdx.x * blockDim.x + threadIdx.x;
    if (i < NL*DS) {
        float nu = expf(nu_log[i]);
        float r  = expf(-nu);
        float th = expf(th_log[i]);
        g_lre[i] = r * cosf(th);
        g_lim[i] = r * sinf(th);
        g_gam[i] = sqrtf(fmaxf(1.0f - r*r, 0.0f));
    }
    if (i < NL) g_sres[i] = 1.0f / (1.0f + expf(-rlog[i]));
}

__global__ void prep_wb_enc_kernel(const float* __restrict__ Bre, const float* __restrict__ Bim,
                                   const float* __restrict__ enc_w) {
    int idx = blockIdx.x * blockDim.x + threadIdx.x;
    if (idx < NL*DM*DM) {
        int l = idx / (DM*DM), rem = idx - l*(DM*DM);
        int n = rem / DM, k = rem - n*DM;
        float v;
        if (n < DS) v = g_gam[l*DS + n]      * Bre[((size_t)l*DS + n)*DM + k];
        else        v = g_gam[l*DS + n - DS] * Bim[((size_t)l*DS + (n-DS))*DM + k];
        split1(v, &g_Wbhi[idx], &g_Wblo[idx]);
    } else {
        int e = idx - NL*DM*DM;
        if (e < DM*DIN) split1(enc_w[e], &g_enchi[e], &g_enclo[e]);
    }
}

__global__ void prep_wc_dec_kernel(const float* __restrict__ Cre, const float* __restrict__ Cim,
                                   const float* __restrict__ dec_w) {
    int idx = blockIdx.x * blockDim.x + threadIdx.x;
    if (idx < NL*DM*DM) {
        int l = idx / (DM*DM), rem = idx - l*(DM*DM);
        int d = rem / DM, k = rem - d*DM;
        float v;
        if (k < DS) v =  Cre[((size_t)l*DM + d)*DS + k];
        else        v = -Cim[((size_t)l*DM + d)*DS + (k-DS)];
        split1(v, &g_Wchi[idx], &g_Wclo[idx]);
    } else {
        int e = idx - NL*DM*DM;
        if (e < 128*DM) {
            int row = e / DM;
            float v = (row < DOUT) ? dec_w[e] : 0.0f;
            split1(v, &g_dechi[e], &g_declo[e]);
        }
    }
}

__global__ void prep_wglu_kernel(const float* __restrict__ W1, const float* __restrict__ W2) {
    int idx = blockIdx.x * blockDim.x + threadIdx.x;
    if (idx >= NL*2*DM*DM) return;
    int l = idx / (2*DM*DM), rem = idx - l*(2*DM*DM);
    int n = rem / DM, k = rem - n*DM;
    int o = n >> 1;
    float v = (n & 1) ? W2[((size_t)l*DM + o)*DM + k]
                      : W1[((size_t)l*DM + o)*DM + k];
    split1(v, &g_Wghi[idx], &g_Wglo[idx]);
}

// ---------------- HMMA GEMM: BK=32, double buffer, 2 CTAs/SM ----------------
// A: fp32 (split inline, register-staged). W: pre-split bf16 hi/lo via cp.async.
// Stage (32KB): A tile 16KB (row: 64B hi | 64B lo), W tile 16KB (same layout).
// EPI: 0 plain, 1 += Dvec[n]*Xres[m,n], 2 GLU: Xout[m,n/2] += s*even*sigmoid(odd)
#define STAGEB 32768

// cp.async W chunk (rows bn..bn+127, K cols k0..k0+31) into stage W region
__device__ __forceinline__ void fill_w_async(const __nv_bfloat16* __restrict__ Whi,
                                             const __nv_bfloat16* __restrict__ Wlo,
                                             int bn, int K, int k0, uint32_t wdst, int tid) {
    const int wrow  = tid >> 1;     // 0..127
    const int whalf = tid & 1;      // 0 hi, 1 lo
    const char* src = (const char*)((whalf ? Wlo : Whi) + (size_t)(bn + wrow)*K + k0);
    const uint32_t b0 = (uint32_t)(wrow*128 + whalf*64);
#pragma unroll
    for (int q = 0; q < 4; q++)
        cpasync16(wdst + sw128(b0 + q*16), src + q*16);
}

template<int EPI, bool WGUARD>
__global__ __launch_bounds__(256, 2)
void hmma_gemm(const float* __restrict__ A,
               const __nv_bfloat16* __restrict__ Whi, const __nv_bfloat16* __restrict__ Wlo,
               float* __restrict__ C, int K, int Ntot,
               const float* __restrict__ Dvec, const float* __restrict__ Xres,
               const float* __restrict__ sres_p, float* __restrict__ Xout) {
    extern __shared__ char smem[];
    const uint32_t s0 = smem_u32(smem);
    const int tid  = threadIdx.x;
    const int wid  = tid >> 5;
    const int lane = tid & 31;
    const int wm   = wid & 1;      // M half (64 rows)
    const int wn   = wid >> 1;     // N quarter (32 cols)
    const int bm   = blockIdx.y * 128;
    const int bn   = blockIdx.x * 128;

    float acc[4][4][4];
#pragma unroll
    for (int i = 0; i < 4; i++)
#pragma unroll
        for (int j = 0; j < 4; j++)
#pragma unroll
            for (int q = 0; q < 4; q++) acc[i][j][q] = 0.0f;

    const int NK = K >> 5;   // chunks of 32
    const int frow = tid >> 2;       // 0..63 (A fill row; +64 second)
    const int fq   = tid & 3;        // 0..3

    // prologue: chunk 0 -> buf 0
    fill_w_async(Whi, Wlo, bn, K, 0, s0 + 16384, tid);
    cp_commit();
    Pack8 pa0 = load_split(A + (size_t)(bm + frow     )*K + fq*8);
    Pack8 pa1 = load_split(A + (size_t)(bm + frow + 64)*K + fq*8);
    store_pair(smem, frow,      fq, pa0);
    store_pair(smem, frow + 64, fq, pa1);
    cp_wait<0>();
    __syncthreads();

    // per-lane ldmatrix address components
    const int a_row = wm*64 + (lane & 7) + ((lane >> 3) & 1)*8;
    const int a_kb  = (lane >> 4) << 4;
    const int b_sub = lane >> 3;
    const int b_row = wn*32 + (lane & 7) + (b_sub >> 1)*8;
    const int b_kb  = (b_sub & 1) << 4;

    for (int t = 0; t < NK; ++t) {
        const int buf = t & 1;
        if (t + 1 < NK) {
            const int k0 = (t + 1) << 5;
            // cp.async W(t+1) into buf^1 (safe: buf^1 readers finished before
            // the trailing sync of iteration t-1)
            fill_w_async(Whi, Wlo, bn, K, k0, s0 + (buf ^ 1)*STAGEB + 16384, tid);
            cp_commit();
            pa0 = load_split(A + (size_t)(bm + frow     )*K + k0 + fq*8);
            pa1 = load_split(A + (size_t)(bm + frow + 64)*K + k0 + fq*8);
        }
        const uint32_t As = s0 + buf*STAGEB;
        const uint32_t Ws = As + 16384;
#pragma unroll
        for (int s = 0; s < 2; ++s) {
            uint32_t bh[4][2], bl[4][2];
#pragma unroll
            for (int jj = 0; jj < 2; jj++) {
                uint32_t base = (uint32_t)((b_row + 16*jj)*128 + s*32 + b_kb);
                uint32_t r[4];
                ldsm4(r, Ws + sw128(base));
                bh[2*jj][0] = r[0]; bh[2*jj][1] = r[1];
                bh[2*jj+1][0] = r[2]; bh[2*jj+1][1] = r[3];
                ldsm4(r, Ws + sw128(base + 64));
                bl[2*jj][0] = r[0]; bl[2*jj][1] = r[1];
                bl[2*jj+1][0] = r[2]; bl[2*jj+1][1] = r[3];
            }
#pragma unroll
            for (int i = 0; i < 4; i++) {
                uint32_t ah[4], al[4];
                uint32_t base = (uint32_t)((a_row + 16*i)*128 + s*32 + a_kb);
                ldsm4(ah, As + sw128(base));
                ldsm4(al, As + sw128(base + 64));
#pragma unroll
                for (int j = 0; j < 4; j++) {
                    mma_bf16(acc[i][j], ah, bh[j]);
                    mma_bf16(acc[i][j], ah, bl[j]);
                    mma_bf16(acc[i][j], al, bh[j]);
                }
            }
        }
        if (t + 1 < NK) {
            char* s2 = smem + (buf ^ 1)*STAGEB;
            __syncthreads();                 // readers done with buf^1
            store_pair(s2, frow,      fq, pa0);
            store_pair(s2, frow + 64, fq, pa1);
            cp_wait<0>();                    // W(t+1) landed
            __syncthreads();                 // buf^1 ready
        }
    }

    // epilogue
    const int gid = lane >> 2;
    const int tg  = lane & 3;
#pragma unroll
    for (int i = 0; i < 4; i++) {
        const int r0 = bm + wm*64 + i*16 + gid;
#pragma unroll
        for (int j = 0; j < 4; j++) {
            const int col = bn + wn*32 + j*8 + tg*2;
            if (EPI == 2) {
                const float s = *sres_p;
                const int oc = col >> 1;
                float* xp0 = Xout + (size_t)r0 * DM + oc;
                float* xp1 = Xout + (size_t)(r0+8) * DM + oc;
                *xp0 = fmaf(s * acc[i][j][0], 1.0f/(1.0f + expf(-acc[i][j][1])), *xp0);
                *xp1 = fmaf(s * acc[i][j][2], 1.0f/(1.0f + expf(-acc[i][j][3])), *xp1);
            } else {
                if (WGUARD && col >= Ntot) continue;
                float2 v0 = make_float2(acc[i][j][0], acc[i][j][1]);
                float2 v1 = make_float2(acc[i][j][2], acc[i][j][3]);
                if (EPI == 1) {
                    const float2 d  = *reinterpret_cast<const float2*>(Dvec + col);
                    const float2 x0 = *reinterpret_cast<const float2*>(Xres + (size_t)r0*Ntot + col);
                    const float2 x1 = *reinterpret_cast<const float2*>(Xres + (size_t)(r0+8)*Ntot + col);
                    v0.x = fmaf(d.x, x0.x, v0.x); v0.y = fmaf(d.y, x0.y, v0.y);
                    v1.x = fmaf(d.x, x1.x, v1.x); v1.y = fmaf(d.y, x1.y, v1.y);
                }
                *reinterpret_cast<float2*>(C + (size_t)r0*Ntot + col)     = v0;
                *reinterpret_cast<float2*>(C + (size_t)(r0+8)*Ntot + col) = v1;
            }
        }
    }
}

// ---------------- chunked LRU scan ----------------
__global__ void scan_local_kernel(const float* __restrict__ Bu, float* __restrict__ H,
                                  const float* __restrict__ lre_g,
                                  const float* __restrict__ lim_g) {
    int n = threadIdx.x;
    int b = blockIdx.x;
    int c = blockIdx.y;
    float lre = lre_g[n], lim = lim_g[n];
    size_t base = ((size_t)b * LSEQ + (size_t)c * CHLEN) * DM + n;
    float hre = 0.0f, him = 0.0f;
#pragma unroll 4
    for (int t = 0; t < CHLEN; ++t) {
        size_t off = base + (size_t)t * DM;
        float bre = Bu[off];
        float bim = Bu[off + DS];
        float nre = fmaf(lre, hre, fmaf(-lim, him, bre));
        float nim = fmaf(lim, hre, fmaf( lre, him, bim));
        hre = nre; him = nim;
        H[off]      = hre;
        H[off + DS] = him;
    }
    int ci = b * NCH + c;
    g_cend[(size_t)ci*2*DS + n]      = hre;
    g_cend[(size_t)ci*2*DS + DS + n] = him;
}

__global__ void scan_carry_kernel(const float* __restrict__ lre_g,
                                  const float* __restrict__ lim_g) {
    int n = threadIdx.x;
    int b = blockIdx.x;
    float lre = lre_g[n], lim = lim_g[n];
    float pre = lre, pim = lim;
#pragma unroll
    for (int i = 0; i < 7; i++) {     // lam^128
        float t = pre*pre - pim*pim;
        pim = 2.0f*pre*pim;
        pre = t;
    }
    float sre = 0.0f, sim = 0.0f;
    for (int c = 0; c < NCH; ++c) {
        size_t ci = (size_t)(b * NCH + c) * 2 * DS;
        g_cin[ci + n]      = sre;
        g_cin[ci + DS + n] = sim;
        float ere = g_cend[ci + n];
        float eim = g_cend[ci + DS + n];
        float nre = fmaf(pre, sre, fmaf(-pim, sim, ere));
        float nim = fmaf(pim, sre, fmaf( pre, sim, eim));
        sre = nre; sim = nim;
    }
}

__global__ void scan_fix_kernel(float* __restrict__ H,
                                const float* __restrict__ lre_g,
                                const float* __restrict__ lim_g) {
    int n = threadIdx.x;
    int b = blockIdx.x;
    int c = blockIdx.y + 1;
    float lre = lre_g[n], lim = lim_g[n];
    size_t ci = (size_t)(b * NCH + c) * 2 * DS;
    float cre = g_cin[ci + n];
    float cim = g_cin[ci + DS + n];
    float pre = lre, pim = lim;
    size_t base = ((size_t)b * LSEQ + (size_t)c * CHLEN) * DM + n;
#pragma unroll 4
    for (int t = 0; t < CHLEN; ++t) {
        size_t off = base + (size_t)t * DM;
        float hre = H[off]      + (pre*cre - pim*cim);
        float him = H[off + DS] + (pre*cim + pim*cre);
        H[off]      = hre;
        H[off + DS] = him;
        float npre = pre*lre - pim*lim;
        float npim = pre*lim + pim*lre;
        pre = npre; pim = npim;
    }
}

// ---------------- host launch ----------------
extern "C" void kernel_launch(void* const* d_in, const int* in_sizes, int n_in,
                              void* d_out, int out_size) {
    const float* u      = (const float*)d_in[0];
    const float* enc_w  = (const float*)d_in[1];
    const float* dec_w  = (const float*)d_in[2];
    const float* nu_log = (const float*)d_in[3];
    const float* th_log = (const float*)d_in[4];
    const float* Bre    = (const float*)d_in[5];
    const float* Bim    = (const float*)d_in[6];
    const float* Cre    = (const float*)d_in[7];
    const float* Cim    = (const float*)d_in[8];
    const float* Dv     = (const float*)d_in[9];
    const float* W1     = (const float*)d_in[10];
    const float* W2     = (const float*)d_in[11];
    const float* rlog   = (const float*)d_in[12];
    float* out = (float*)d_out;

    float *px, *pbu, *ph, *pz, *plre, *plim, *psres;
    __nv_bfloat16 *pWbhi, *pWblo, *pWchi, *pWclo, *pWghi, *pWglo;
    __nv_bfloat16 *penchi, *penclo, *pdechi, *pdeclo;
    cudaGetSymbolAddress((void**)&px,   g_x);
    cudaGetSymbolAddress((void**)&pbu,  g_bu);
    cudaGetSymbolAddress((void**)&ph,   g_h);
    cudaGetSymbolAddress((void**)&pz,   g_z);
    cudaGetSymbolAddress((void**)&pWbhi, g_Wbhi); cudaGetSymbolAddress((void**)&pWblo, g_Wblo);
    cudaGetSymbolAddress((void**)&pWchi, g_Wchi); cudaGetSymbolAddress((void**)&pWclo, g_Wclo);
    cudaGetSymbolAddress((void**)&pWghi, g_Wghi); cudaGetSymbolAddress((void**)&pWglo, g_Wglo);
    cudaGetSymbolAddress((void**)&penchi, g_enchi); cudaGetSymbolAddress((void**)&penclo, g_enclo);
    cudaGetSymbolAddress((void**)&pdechi, g_dechi); cudaGetSymbolAddress((void**)&pdeclo, g_declo);
    cudaGetSymbolAddress((void**)&plre,  g_lre);
    cudaGetSymbolAddress((void**)&plim,  g_lim);
    cudaGetSymbolAddress((void**)&psres, g_sres);

    const int SMEM = 2 * STAGEB;   // 64 KB per CTA
    cudaFuncSetAttribute(hmma_gemm<0,false>, cudaFuncAttributeMaxDynamicSharedMemorySize, SMEM);
    cudaFuncSetAttribute(hmma_gemm<1,false>, cudaFuncAttributeMaxDynamicSharedMemorySize, SMEM);
    cudaFuncSetAttribute(hmma_gemm<2,false>, cudaFuncAttributeMaxDynamicSharedMemorySize, SMEM);
    cudaFuncSetAttribute(hmma_gemm<0,true>,  cudaFuncAttributeMaxDynamicSharedMemorySize, SMEM);

    // prep (4 launches)
    prep_lam_kernel   <<<(NL*DS + 255)/256, 256>>>(nu_log, th_log, rlog);
    prep_wb_enc_kernel<<<(NL*DM*DM + DM*DIN + 255)/256, 256>>>(Bre, Bim, enc_w);
    prep_wc_dec_kernel<<<(NL*DM*DM + 128*DM + 255)/256, 256>>>(Cre, Cim, dec_w);
    prep_wglu_kernel  <<<(NL*2*DM*DM + 255)/256, 256>>>(W1, W2);

    // encoder: x = u @ enc_w^T  (K=64)
    hmma_gemm<0,false><<<dim3(DM/128, MTOK/128), 256, SMEM>>>(
        u, penchi, penclo, px, DIN, DM, nullptr, nullptr, nullptr, nullptr);

    for (int l = 0; l < NL; ++l) {
        const float* lre = plre + l*DS;
        const float* lim = plim + l*DS;
        // Bu = x @ Wb^T (gamma folded)
        hmma_gemm<0,false><<<dim3(DM/128, MTOK/128), 256, SMEM>>>(
            px, pWbhi + (size_t)l*DM*DM, pWblo + (size_t)l*DM*DM,
            pbu, DM, DM, nullptr, nullptr, nullptr, nullptr);
        scan_local_kernel<<<dim3(NB, NCH), DS>>>(pbu, ph, lre, lim);
        scan_carry_kernel<<<NB, DS>>>(lre, lim);
        scan_fix_kernel<<<dim3(NB, NCH-1), DS>>>(ph, lre, lim);
        // z = Re(C h) + D*x
        hmma_gemm<1,false><<<dim3(DM/128, MTOK/128), 256, SMEM>>>(
            ph, pWchi + (size_t)l*DM*DM, pWclo + (size_t)l*DM*DM,
            pz, DM, DM, Dv + l*DM, px, nullptr, nullptr);
        // GLU GEMM (N=1024 interleaved): x += s*g1*sigmoid(g2)
        hmma_gemm<2,false><<<dim3(2*DM/128, MTOK/128), 256, SMEM>>>(
            pz, pWghi + (size_t)l*2*DM*DM, pWglo + (size_t)l*2*DM*DM,
            nullptr, DM, 2*DM, nullptr, nullptr, psres + l, px);
    }

    // decoder: out = x @ dec_w^T (N=64 guarded; weights padded to 128 rows)
    hmma_gemm<0,true><<<dim3(1, MTOK/128), 256, SMEM>>>(
        px, pdechi, pdeclo, out, DM, DOUT, nullptr, nullptr, nullptr, nullptr);
}

// round 9
// speedup vs baseline: 1.6562x; 1.1541x over previous
#include <cuda_runtime.h>
#include <cuda_fp16.h>
#include <math.h>
#include <string.h>
#include <stdint.h>

#define NB    8
#define LSEQ  2048
#define MTOK  (NB*LSEQ)     // 16384 tokens
#define DIN   64
#define DOUT  64
#define DM    512
#define DS    256
#define NL    4
#define NCH   16
#define CHLEN (LSEQ/NCH)    // 128

// ---------------- scratch (device globals; no allocation allowed) ----------------
__device__ float g_x [MTOK*DM];
__device__ float g_bu[MTOK*DM];           // Bu packed [re(256) | im(256)]
__device__ float g_h [MTOK*DM];           // h  packed [re | im]
__device__ float g_z [MTOK*DM];           // LRU output
// pre-split weights (fp16 hi/lo)
__device__ __half g_Wbhi[NL*DM*DM],   g_Wblo[NL*DM*DM];
__device__ __half g_Wchi[NL*DM*DM],   g_Wclo[NL*DM*DM];
__device__ __half g_Wghi[NL*2*DM*DM], g_Wglo[NL*2*DM*DM];
__device__ __half g_enchi[DM*DIN],    g_enclo[DM*DIN];
__device__ __half g_dechi[128*DM],    g_declo[128*DM];   // padded to 128 rows
// scan params / carries
__device__ float g_lre[NL*DS], g_lim[NL*DS], g_gam[NL*DS], g_sres[NL];
__device__ float g_cend[NB*NCH*2*DS], g_cin[NB*NCH*2*DS];

// ---------------- helpers ----------------
__device__ __forceinline__ uint32_t smem_u32(const void* p) {
    uint32_t a;
    asm("{ .reg .u64 t; cvta.to.shared.u64 t, %1; cvt.u32.u64 %0, t; }" : "=r"(a) : "l"(p));
    return a;
}
__device__ __forceinline__ uint32_t sw128(uint32_t b) { return b ^ ((b >> 3) & 0x70); }

__device__ __forceinline__ void ldsm4(uint32_t* r, uint32_t addr) {
    asm volatile("ldmatrix.sync.aligned.m8n8.x4.shared.b16 {%0,%1,%2,%3}, [%4];"
                 : "=r"(r[0]), "=r"(r[1]), "=r"(r[2]), "=r"(r[3]) : "r"(addr));
}
__device__ __forceinline__ void mma_f16(float* c, const uint32_t* a, const uint32_t* b) {
    asm volatile(
        "mma.sync.aligned.m16n8k16.row.col.f32.f16.f16.f32 "
        "{%0,%1,%2,%3}, {%4,%5,%6,%7}, {%8,%9}, {%0,%1,%2,%3};"
        : "+f"(c[0]), "+f"(c[1]), "+f"(c[2]), "+f"(c[3])
        : "r"(a[0]), "r"(a[1]), "r"(a[2]), "r"(a[3]), "r"(b[0]), "r"(b[1]));
}
__device__ __forceinline__ void cpasync16(uint32_t d, const void* s) {
    asm volatile("cp.async.cg.shared.global [%0], [%1], 16;" :: "r"(d), "l"(s));
}
__device__ __forceinline__ void cp_commit() { asm volatile("cp.async.commit_group;" ::: "memory"); }
template<int N> __device__ __forceinline__ void cp_wait() {
    asm volatile("cp.async.wait_group %0;" :: "n"(N) : "memory");
}

__device__ __forceinline__ uint32_t pkh(float a, float b) {
    __half2 t = __floats2half2_rn(a, b);
    uint32_t u; memcpy(&u, &t, 4); return u;
}

// load 8 fp32 -> 8 fp16 (16B)
__device__ __forceinline__ uint4 load_h8(const float* p) {
    float4 v0 = *reinterpret_cast<const float4*>(p);
    float4 v1 = *reinterpret_cast<const float4*>(p + 4);
    uint4 o;
    o.x = pkh(v0.x, v0.y); o.y = pkh(v0.z, v0.w);
    o.z = pkh(v1.x, v1.y); o.w = pkh(v1.z, v1.w);
    return o;
}

__device__ __forceinline__ void split1h(float v, __half* h, __half* l) {
    __half hh = __float2half_rn(v);
    *h = hh;
    *l = __float2half_rn(v - __half2float(hh));
}

// ---------------- prep kernels (merged) ----------------
__global__ void prep_lam_kernel(const float* __restrict__ nu_log,
                                const float* __restrict__ th_log,
                                const float* __restrict__ rlog) {
    int i = blockIdx.x * blockDim.x + threadIdx.x;
    if (i < NL*DS) {
        float nu = expf(nu_log[i]);
        float r  = expf(-nu);
        float th = expf(th_log[i]);
        g_lre[i] = r * cosf(th);
        g_lim[i] = r * sinf(th);
        g_gam[i] = sqrtf(fmaxf(1.0f - r*r, 0.0f));
    }
    if (i < NL) g_sres[i] = 1.0f / (1.0f + expf(-rlog[i]));
}

__global__ void prep_wb_enc_kernel(const float* __restrict__ Bre, const float* __restrict__ Bim,
                                   const float* __restrict__ enc_w) {
    int idx = blockIdx.x * blockDim.x + threadIdx.x;
    if (idx < NL*DM*DM) {
        int l = idx / (DM*DM), rem = idx - l*(DM*DM);
        int n = rem / DM, k = rem - n*DM;
        float v;
        if (n < DS) v = g_gam[l*DS + n]      * Bre[((size_t)l*DS + n)*DM + k];
        else        v = g_gam[l*DS + n - DS] * Bim[((size_t)l*DS + (n-DS))*DM + k];
        split1h(v, &g_Wbhi[idx], &g_Wblo[idx]);
    } else {
        int e = idx - NL*DM*DM;
        if (e < DM*DIN) split1h(enc_w[e], &g_enchi[e], &g_enclo[e]);
    }
}

__global__ void prep_wc_dec_kernel(const float* __restrict__ Cre, const float* __restrict__ Cim,
                                   const float* __restrict__ dec_w) {
    int idx = blockIdx.x * blockDim.x + threadIdx.x;
    if (idx < NL*DM*DM) {
        int l = idx / (DM*DM), rem = idx - l*(DM*DM);
        int d = rem / DM, k = rem - d*DM;
        float v;
        if (k < DS) v =  Cre[((size_t)l*DM + d)*DS + k];
        else        v = -Cim[((size_t)l*DM + d)*DS + (k-DS)];
        split1h(v, &g_Wchi[idx], &g_Wclo[idx]);
    } else {
        int e = idx - NL*DM*DM;
        if (e < 128*DM) {
            int row = e / DM;
            float v = (row < DOUT) ? dec_w[e] : 0.0f;
            split1h(v, &g_dechi[e], &g_declo[e]);
        }
    }
}

__global__ void prep_wglu_kernel(const float* __restrict__ W1, const float* __restrict__ W2) {
    int idx = blockIdx.x * blockDim.x + threadIdx.x;
    if (idx >= NL*2*DM*DM) return;
    int l = idx / (2*DM*DM), rem = idx - l*(2*DM*DM);
    int n = rem / DM, k = rem - n*DM;
    int o = n >> 1;
    float v = (n & 1) ? W2[((size_t)l*DM + o)*DM + k]
                      : W1[((size_t)l*DM + o)*DM + k];
    split1h(v, &g_Wghi[idx], &g_Wglo[idx]);
}

// ---------------- HMMA GEMM: fp16 A (single), fp16 W (hi+lo), 2 MMAs/tile ----
// A: fp32 -> fp16 inline (no residual). W: pre-split fp16 hi/lo via cp.async.
// Stage (32KB): A tile 16KB (row: 64B fp16 | 64B unused), W tile 16KB (64B hi | 64B lo).
// EPI: 0 plain, 1 += Dvec[n]*Xres[m,n], 2 GLU: Xout[m,n/2] += s*even*sigmoid(odd)
#define STAGEB 32768

__device__ __forceinline__ void fill_w_async(const __half* __restrict__ Whi,
                                             const __half* __restrict__ Wlo,
                                             int bn, int K, int k0, uint32_t wdst, int tid) {
    const int wrow  = tid >> 1;     // 0..127
    const int whalf = tid & 1;      // 0 hi, 1 lo
    const char* src = (const char*)((whalf ? Wlo : Whi) + (size_t)(bn + wrow)*K + k0);
    const uint32_t b0 = (uint32_t)(wrow*128 + whalf*64);
#pragma unroll
    for (int q = 0; q < 4; q++)
        cpasync16(wdst + sw128(b0 + q*16), src + q*16);
}

template<int EPI, bool WGUARD>
__global__ __launch_bounds__(256, 2)
void hmma_gemm(const float* __restrict__ A,
               const __half* __restrict__ Whi, const __half* __restrict__ Wlo,
               float* __restrict__ C, int K, int Ntot,
               const float* __restrict__ Dvec, const float* __restrict__ Xres,
               const float* __restrict__ sres_p, float* __restrict__ Xout) {
    extern __shared__ char smem[];
    const uint32_t s0 = smem_u32(smem);
    const int tid  = threadIdx.x;
    const int wid  = tid >> 5;
    const int lane = tid & 31;
    const int wm   = wid & 1;      // M half (64 rows)
    const int wn   = wid >> 1;     // N quarter (32 cols)
    const int bm   = blockIdx.y * 128;
    const int bn   = blockIdx.x * 128;

    float acc[4][4][4];
#pragma unroll
    for (int i = 0; i < 4; i++)
#pragma unroll
        for (int j = 0; j < 4; j++)
#pragma unroll
            for (int q = 0; q < 4; q++) acc[i][j][q] = 0.0f;

    const int NK = K >> 5;   // chunks of 32
    const int frow = tid >> 2;       // 0..63 (A fill row; +64 second)
    const int fq   = tid & 3;        // 0..3

    // prologue: chunk 0 -> buf 0
    fill_w_async(Whi, Wlo, bn, K, 0, s0 + 16384, tid);
    cp_commit();
    uint4 pa0 = load_h8(A + (size_t)(bm + frow     )*K + fq*8);
    uint4 pa1 = load_h8(A + (size_t)(bm + frow + 64)*K + fq*8);
    *reinterpret_cast<uint4*>(smem + sw128((uint32_t)(frow*128 + fq*16)))        = pa0;
    *reinterpret_cast<uint4*>(smem + sw128((uint32_t)((frow+64)*128 + fq*16)))   = pa1;
    cp_wait<0>();
    __syncthreads();

    // per-lane ldmatrix address components
    const int a_row = wm*64 + (lane & 7) + ((lane >> 3) & 1)*8;
    const int a_kb  = (lane >> 4) << 4;
    const int b_sub = lane >> 3;
    const int b_row = wn*32 + (lane & 7) + (b_sub >> 1)*8;
    const int b_kb  = (b_sub & 1) << 4;

    for (int t = 0; t < NK; ++t) {
        const int buf = t & 1;
        if (t + 1 < NK) {
            const int k0 = (t + 1) << 5;
            fill_w_async(Whi, Wlo, bn, K, k0, s0 + (buf ^ 1)*STAGEB + 16384, tid);
            cp_commit();
            pa0 = load_h8(A + (size_t)(bm + frow     )*K + k0 + fq*8);
            pa1 = load_h8(A + (size_t)(bm + frow + 64)*K + k0 + fq*8);
        }
        const uint32_t As = s0 + buf*STAGEB;
        const uint32_t Ws = As + 16384;
#pragma unroll
        for (int s = 0; s < 2; ++s) {
            uint32_t bh[4][2], bl[4][2];
#pragma unroll
            for (int jj = 0; jj < 2; jj++) {
                uint32_t base = (uint32_t)((b_row + 16*jj)*128 + s*32 + b_kb);
                uint32_t r[4];
                ldsm4(r, Ws + sw128(base));
                bh[2*jj][0] = r[0]; bh[2*jj][1] = r[1];
                bh[2*jj+1][0] = r[2]; bh[2*jj+1][1] = r[3];
                ldsm4(r, Ws + sw128(base + 64));
                bl[2*jj][0] = r[0]; bl[2*jj][1] = r[1];
                bl[2*jj+1][0] = r[2]; bl[2*jj+1][1] = r[3];
            }
#pragma unroll
            for (int i = 0; i < 4; i++) {
                uint32_t ah[4];
                uint32_t base = (uint32_t)((a_row + 16*i)*128 + s*32 + a_kb);
                ldsm4(ah, As + sw128(base));
#pragma unroll
                for (int j = 0; j < 4; j++) {
                    mma_f16(acc[i][j], ah, bh[j]);
                    mma_f16(acc[i][j], ah, bl[j]);
                }
            }
        }
        if (t + 1 < NK) {
            char* s2 = smem + (buf ^ 1)*STAGEB;
            __syncthreads();                 // readers done with buf^1
            *reinterpret_cast<uint4*>(s2 + sw128((uint32_t)(frow*128 + fq*16)))      = pa0;
            *reinterpret_cast<uint4*>(s2 + sw128((uint32_t)((frow+64)*128 + fq*16))) = pa1;
            cp_wait<0>();                    // W(t+1) landed
            __syncthreads();                 // buf^1 ready
        }
    }

    // epilogue
    const int gid = lane >> 2;
    const int tg  = lane & 3;
#pragma unroll
    for (int i = 0; i < 4; i++) {
        const int r0 = bm + wm*64 + i*16 + gid;
#pragma unroll
        for (int j = 0; j < 4; j++) {
            const int col = bn + wn*32 + j*8 + tg*2;
            if (EPI == 2) {
                const float s = *sres_p;
                const int oc = col >> 1;
                float* xp0 = Xout + (size_t)r0 * DM + oc;
                float* xp1 = Xout + (size_t)(r0+8) * DM + oc;
                *xp0 = fmaf(s * acc[i][j][0], 1.0f/(1.0f + expf(-acc[i][j][1])), *xp0);
                *xp1 = fmaf(s * acc[i][j][2], 1.0f/(1.0f + expf(-acc[i][j][3])), *xp1);
            } else {
                if (WGUARD && col >= Ntot) continue;
                float2 v0 = make_float2(acc[i][j][0], acc[i][j][1]);
                float2 v1 = make_float2(acc[i][j][2], acc[i][j][3]);
                if (EPI == 1) {
                    const float2 d  = *reinterpret_cast<const float2*>(Dvec + col);
                    const float2 x0 = *reinterpret_cast<const float2*>(Xres + (size_t)r0*Ntot + col);
                    const float2 x1 = *reinterpret_cast<const float2*>(Xres + (size_t)(r0+8)*Ntot + col);
                    v0.x = fmaf(d.x, x0.x, v0.x); v0.y = fmaf(d.y, x0.y, v0.y);
                    v1.x = fmaf(d.x, x1.x, v1.x); v1.y = fmaf(d.y, x1.y, v1.y);
                }
                *reinterpret_cast<float2*>(C + (size_t)r0*Ntot + col)     = v0;
                *reinterpret_cast<float2*>(C + (size_t)(r0+8)*Ntot + col) = v1;
            }
        }
    }
}

// ---------------- chunked LRU scan ----------------
__global__ void scan_local_kernel(const float* __restrict__ Bu, float* __restrict__ H,
                                  const float* __restrict__ lre_g,
                                  const float* __restrict__ lim_g) {
    int n = threadIdx.x;
    int b = blockIdx.x;
    int c = blockIdx.y;
    float lre = lre_g[n], lim = lim_g[n];
    size_t base = ((size_t)b * LSEQ + (size_t)c * CHLEN) * DM + n;
    float hre = 0.0f, him = 0.0f;
#pragma unroll 4
    for (int t = 0; t < CHLEN; ++t) {
        size_t off = base + (size_t)t * DM;
        float bre = Bu[off];
        float bim = Bu[off + DS];
        float nre = fmaf(lre, hre, fmaf(-lim, him, bre));
        float nim = fmaf(lim, hre, fmaf( lre, him, bim));
        hre = nre; him = nim;
        H[off]      = hre;
        H[off + DS] = him;
    }
    int ci = b * NCH + c;
    g_cend[(size_t)ci*2*DS + n]      = hre;
    g_cend[(size_t)ci*2*DS + DS + n] = him;
}

__global__ void scan_carry_kernel(const float* __restrict__ lre_g,
                                  const float* __restrict__ lim_g) {
    int n = threadIdx.x;
    int b = blockIdx.x;
    float lre = lre_g[n], lim = lim_g[n];
    float pre = lre, pim = lim;
#pragma unroll
    for (int i = 0; i < 7; i++) {     // lam^128
        float t = pre*pre - pim*pim;
        pim = 2.0f*pre*pim;
        pre = t;
    }
    float sre = 0.0f, sim = 0.0f;
    for (int c = 0; c < NCH; ++c) {
        size_t ci = (size_t)(b * NCH + c) * 2 * DS;
        g_cin[ci + n]      = sre;
        g_cin[ci + DS + n] = sim;
        float ere = g_cend[ci + n];
        float eim = g_cend[ci + DS + n];
        float nre = fmaf(pre, sre, fmaf(-pim, sim, ere));
        float nim = fmaf(pim, sre, fmaf( pre, sim, eim));
        sre = nre; sim = nim;
    }
}

__global__ void scan_fix_kernel(float* __restrict__ H,
                                const float* __restrict__ lre_g,
                                const float* __restrict__ lim_g) {
    int n = threadIdx.x;
    int b = blockIdx.x;
    int c = blockIdx.y + 1;
    float lre = lre_g[n], lim = lim_g[n];
    size_t ci = (size_t)(b * NCH + c) * 2 * DS;
    float cre = g_cin[ci + n];
    float cim = g_cin[ci + DS + n];
    float pre = lre, pim = lim;
    size_t base = ((size_t)b * LSEQ + (size_t)c * CHLEN) * DM + n;
#pragma unroll 4
    for (int t = 0; t < CHLEN; ++t) {
        size_t off = base + (size_t)t * DM;
        float hre = H[off]      + (pre*cre - pim*cim);
        float him = H[off + DS] + (pre*cim + pim*cre);
        H[off]      = hre;
        H[off + DS] = him;
        float npre = pre*lre - pim*lim;
        float npim = pre*lim + pim*lre;
        pre = npre; pim = npim;
    }
}

// ---------------- host launch ----------------
extern "C" void kernel_launch(void* const* d_in, const int* in_sizes, int n_in,
                              void* d_out, int out_size) {
    const float* u      = (const float*)d_in[0];
    const float* enc_w  = (const float*)d_in[1];
    const float* dec_w  = (const float*)d_in[2];
    const float* nu_log = (const float*)d_in[3];
    const float* th_log = (const float*)d_in[4];
    const float* Bre    = (const float*)d_in[5];
    const float* Bim    = (const float*)d_in[6];
    const float* Cre    = (const float*)d_in[7];
    const float* Cim    = (const float*)d_in[8];
    const float* Dv     = (const float*)d_in[9];
    const float* W1     = (const float*)d_in[10];
    const float* W2     = (const float*)d_in[11];
    const float* rlog   = (const float*)d_in[12];
    float* out = (float*)d_out;

    float *px, *pbu, *ph, *pz, *plre, *plim, *psres;
    __half *pWbhi, *pWblo, *pWchi, *pWclo, *pWghi, *pWglo;
    __half *penchi, *penclo, *pdechi, *pdeclo;
    cudaGetSymbolAddress((void**)&px,   g_x);
    cudaGetSymbolAddress((void**)&pbu,  g_bu);
    cudaGetSymbolAddress((void**)&ph,   g_h);
    cudaGetSymbolAddress((void**)&pz,   g_z);
    cudaGetSymbolAddress((void**)&pWbhi, g_Wbhi); cudaGetSymbolAddress((void**)&pWblo, g_Wblo);
    cudaGetSymbolAddress((void**)&pWchi, g_Wchi); cudaGetSymbolAddress((void**)&pWclo, g_Wclo);
    cudaGetSymbolAddress((void**)&pWghi, g_Wghi); cudaGetSymbolAddress((void**)&pWglo, g_Wglo);
    cudaGetSymbolAddress((void**)&penchi, g_enchi); cudaGetSymbolAddress((void**)&penclo, g_enclo);
    cudaGetSymbolAddress((void**)&pdechi, g_dechi); cudaGetSymbolAddress((void**)&pdeclo, g_declo);
    cudaGetSymbolAddress((void**)&plre,  g_lre);
    cudaGetSymbolAddress((void**)&plim,  g_lim);
    cudaGetSymbolAddress((void**)&psres, g_sres);

    const int SMEM = 2 * STAGEB;   // 64 KB per CTA -> 2 CTAs/SM
    cudaFuncSetAttribute(hmma_gemm<0,false>, cudaFuncAttributeMaxDynamicSharedMemorySize, SMEM);
    cudaFuncSetAttribute(hmma_gemm<1,false>, cudaFuncAttributeMaxDynamicSharedMemorySize, SMEM);
    cudaFuncSetAttribute(hmma_gemm<2,false>, cudaFuncAttributeMaxDynamicSharedMemorySize, SMEM);
    cudaFuncSetAttribute(hmma_gemm<0,true>,  cudaFuncAttributeMaxDynamicSharedMemorySize, SMEM);

    // prep (4 launches)
    prep_lam_kernel   <<<(NL*DS + 255)/256, 256>>>(nu_log, th_log, rlog);
    prep_wb_enc_kernel<<<(NL*DM*DM + DM*DIN + 255)/256, 256>>>(Bre, Bim, enc_w);
    prep_wc_dec_kernel<<<(NL*DM*DM + 128*DM + 255)/256, 256>>>(Cre, Cim, dec_w);
    prep_wglu_kernel  <<<(NL*2*DM*DM + 255)/256, 256>>>(W1, W2);

    // encoder: x = u @ enc_w^T  (K=64)
    hmma_gemm<0,false><<<dim3(DM/128, MTOK/128), 256, SMEM>>>(
        u, penchi, penclo, px, DIN, DM, nullptr, nullptr, nullptr, nullptr);

    for (int l = 0; l < NL; ++l) {
        const float* lre = plre + l*DS;
        const float* lim = plim + l*DS;
        // Bu = x @ Wb^T (gamma folded)
        hmma_gemm<0,false><<<dim3(DM/128, MTOK/128), 256, SMEM>>>(
            px, pWbhi + (size_t)l*DM*DM, pWblo + (size_t)l*DM*DM,
            pbu, DM, DM, nullptr, nullptr, nullptr, nullptr);
        scan_local_kernel<<<dim3(NB, NCH), DS>>>(pbu, ph, lre, lim);
        scan_carry_kernel<<<NB, DS>>>(lre, lim);
        scan_fix_kernel<<<dim3(NB, NCH-1), DS>>>(ph, lre, lim);
        // z = Re(C h) + D*x
        hmma_gemm<1,false><<<dim3(DM/128, MTOK/128), 256, SMEM>>>(
            ph, pWchi + (size_t)l*DM*DM, pWclo + (size_t)l*DM*DM,
            pz, DM, DM, Dv + l*DM, px, nullptr, nullptr);
        // GLU GEMM (N=1024 interleaved): x += s*g1*sigmoid(g2)
        hmma_gemm<2,false><<<dim3(2*DM/128, MTOK/128), 256, SMEM>>>(
            pz, pWghi + (size_t)l*2*DM*DM, pWglo + (size_t)l*2*DM*DM,
            nullptr, DM, 2*DM, nullptr, nullptr, psres + l, px);
    }

    // decoder: out = x @ dec_w^T (N=64 guarded; weights padded to 128 rows)
    hmma_gemm<0,true><<<dim3(1, MTOK/128), 256, SMEM>>>(
        px, pdechi, pdeclo, out, DM, DOUT, nullptr, nullptr, nullptr, nullptr);
}

// round 10
// speedup vs baseline: 1.9567x; 1.1815x over previous
#include <cuda_runtime.h>
#include <cuda_fp16.h>
#include <math.h>
#include <string.h>
#include <stdint.h>

#define NB    8
#define LSEQ  2048
#define MTOK  (NB*LSEQ)     // 16384 tokens
#define DIN   64
#define DOUT  64
#define DM    512
#define DS    256
#define NL    4
#define NCH   16
#define CHLEN (LSEQ/NCH)    // 128

// ---------------- scratch (device globals; no allocation allowed) ----------------
__device__ float g_x [MTOK*DM];
__device__ float g_bu[MTOK*DM];           // Bu packed [re(256) | im(256)]
__device__ float g_h [MTOK*DM];           // h  packed [re | im]
__device__ float g_z [MTOK*DM];           // LRU output
// pre-split weights (fp16 hi/lo; GLU is hi-only)
__device__ __half g_Wbhi[NL*DM*DM],   g_Wblo[NL*DM*DM];
__device__ __half g_Wchi[NL*DM*DM],   g_Wclo[NL*DM*DM];
__device__ __half g_Wghi[NL*2*DM*DM];
__device__ __half g_enchi[DM*DIN],    g_enclo[DM*DIN];
__device__ __half g_dechi[128*DM],    g_declo[128*DM];   // padded to 128 rows
// scan params / carries
__device__ float g_lre[NL*DS], g_lim[NL*DS], g_gam[NL*DS], g_sres[NL];
__device__ float g_cend[NB*NCH*2*DS];

// ---------------- helpers ----------------
__device__ __forceinline__ uint32_t smem_u32(const void* p) {
    uint32_t a;
    asm("{ .reg .u64 t; cvta.to.shared.u64 t, %1; cvt.u32.u64 %0, t; }" : "=r"(a) : "l"(p));
    return a;
}
__device__ __forceinline__ uint32_t sw128(uint32_t b) { return b ^ ((b >> 3) & 0x70); }

__device__ __forceinline__ void ldsm4(uint32_t* r, uint32_t addr) {
    asm volatile("ldmatrix.sync.aligned.m8n8.x4.shared.b16 {%0,%1,%2,%3}, [%4];"
                 : "=r"(r[0]), "=r"(r[1]), "=r"(r[2]), "=r"(r[3]) : "r"(addr));
}
__device__ __forceinline__ void mma_f16(float* c, const uint32_t* a, const uint32_t* b) {
    asm volatile(
        "mma.sync.aligned.m16n8k16.row.col.f32.f16.f16.f32 "
        "{%0,%1,%2,%3}, {%4,%5,%6,%7}, {%8,%9}, {%0,%1,%2,%3};"
        : "+f"(c[0]), "+f"(c[1]), "+f"(c[2]), "+f"(c[3])
        : "r"(a[0]), "r"(a[1]), "r"(a[2]), "r"(a[3]), "r"(b[0]), "r"(b[1]));
}
__device__ __forceinline__ void cpasync16(uint32_t d, const void* s) {
    asm volatile("cp.async.cg.shared.global [%0], [%1], 16;" :: "r"(d), "l"(s));
}
__device__ __forceinline__ void cp_commit() { asm volatile("cp.async.commit_group;" ::: "memory"); }
template<int N> __device__ __forceinline__ void cp_wait() {
    asm volatile("cp.async.wait_group %0;" :: "n"(N) : "memory");
}

__device__ __forceinline__ uint32_t pkh(float a, float b) {
    __half2 t = __floats2half2_rn(a, b);
    uint32_t u; memcpy(&u, &t, 4); return u;
}

// load 8 fp32 -> 8 fp16 (16B)
__device__ __forceinline__ uint4 load_h8(const float* p) {
    float4 v0 = *reinterpret_cast<const float4*>(p);
    float4 v1 = *reinterpret_cast<const float4*>(p + 4);
    uint4 o;
    o.x = pkh(v0.x, v0.y); o.y = pkh(v0.z, v0.w);
    o.z = pkh(v1.x, v1.y); o.w = pkh(v1.z, v1.w);
    return o;
}

__device__ __forceinline__ void split1h(float v, __half* h, __half* l) {
    __half hh = __float2half_rn(v);
    *h = hh;
    *l = __float2half_rn(v - __half2float(hh));
}

// ---------------- prep kernels (merged) ----------------
__global__ void prep_lam_kernel(const float* __restrict__ nu_log,
                                const float* __restrict__ th_log,
                                const float* __restrict__ rlog) {
    int i = blockIdx.x * blockDim.x + threadIdx.x;
    if (i < NL*DS) {
        float nu = expf(nu_log[i]);
        float r  = expf(-nu);
        float th = expf(th_log[i]);
        g_lre[i] = r * cosf(th);
        g_lim[i] = r * sinf(th);
        g_gam[i] = sqrtf(fmaxf(1.0f - r*r, 0.0f));
    }
    if (i < NL) g_sres[i] = 1.0f / (1.0f + expf(-rlog[i]));
}

__global__ void prep_wb_enc_kernel(const float* __restrict__ Bre, const float* __restrict__ Bim,
                                   const float* __restrict__ enc_w) {
    int idx = blockIdx.x * blockDim.x + threadIdx.x;
    if (idx < NL*DM*DM) {
        int l = idx / (DM*DM), rem = idx - l*(DM*DM);
        int n = rem / DM, k = rem - n*DM;
        float v;
        if (n < DS) v = g_gam[l*DS + n]      * Bre[((size_t)l*DS + n)*DM + k];
        else        v = g_gam[l*DS + n - DS] * Bim[((size_t)l*DS + (n-DS))*DM + k];
        split1h(v, &g_Wbhi[idx], &g_Wblo[idx]);
    } else {
        int e = idx - NL*DM*DM;
        if (e < DM*DIN) split1h(enc_w[e], &g_enchi[e], &g_enclo[e]);
    }
}

__global__ void prep_wc_dec_kernel(const float* __restrict__ Cre, const float* __restrict__ Cim,
                                   const float* __restrict__ dec_w) {
    int idx = blockIdx.x * blockDim.x + threadIdx.x;
    if (idx < NL*DM*DM) {
        int l = idx / (DM*DM), rem = idx - l*(DM*DM);
        int d = rem / DM, k = rem - d*DM;
        float v;
        if (k < DS) v =  Cre[((size_t)l*DM + d)*DS + k];
        else        v = -Cim[((size_t)l*DM + d)*DS + (k-DS)];
        split1h(v, &g_Wchi[idx], &g_Wclo[idx]);
    } else {
        int e = idx - NL*DM*DM;
        if (e < 128*DM) {
            int row = e / DM;
            float v = (row < DOUT) ? dec_w[e] : 0.0f;
            split1h(v, &g_dechi[e], &g_declo[e]);
        }
    }
}

__global__ void prep_wglu_kernel(const float* __restrict__ W1, const float* __restrict__ W2) {
    int idx = blockIdx.x * blockDim.x + threadIdx.x;
    if (idx >= NL*2*DM*DM) return;
    int l = idx / (2*DM*DM), rem = idx - l*(2*DM*DM);
    int n = rem / DM, k = rem - n*DM;
    int o = n >> 1;
    float v = (n & 1) ? W2[((size_t)l*DM + o)*DM + k]
                      : W1[((size_t)l*DM + o)*DM + k];
    g_Wghi[idx] = __float2half_rn(v);    // GLU uses single-fp16 W
}

// ---------------- HMMA GEMM ----------------
// A: fp32 -> fp16 inline. W: fp16 hi(+lo if WLO) via cp.async.
// Stage (32KB): A tile 16KB, W tile 16KB (64B hi | 64B lo per row).
// EPI: 0 plain, 1 += Dvec[n]*Xres[m,n], 2 GLU: Xout[m,n/2] += s*even*sigmoid(odd)
#define STAGEB 32768

template<bool WLO>
__device__ __forceinline__ void fill_w_async(const __half* __restrict__ Whi,
                                             const __half* __restrict__ Wlo,
                                             int bn, int K, int k0, uint32_t wdst, int tid) {
    if (WLO) {
        const int wrow  = tid >> 1;     // 0..127
        const int whalf = tid & 1;      // 0 hi, 1 lo
        const char* src = (const char*)((whalf ? Wlo : Whi) + (size_t)(bn + wrow)*K + k0);
        const uint32_t b0 = (uint32_t)(wrow*128 + whalf*64);
#pragma unroll
        for (int q = 0; q < 4; q++)
            cpasync16(wdst + sw128(b0 + q*16), src + q*16);
    } else {
        const int wrow = tid >> 1;      // 0..127
        const int part = tid & 1;       // half of the 64B hi row
        const char* src = (const char*)(Whi + (size_t)(bn + wrow)*K + k0 + part*16);
        const uint32_t b0 = (uint32_t)(wrow*128 + part*32);
#pragma unroll
        for (int q = 0; q < 2; q++)
            cpasync16(wdst + sw128(b0 + q*16), src + q*16);
    }
}

template<int EPI, bool WGUARD, bool WLO>
__global__ __launch_bounds__(256, 2)
void hmma_gemm(const float* __restrict__ A,
               const __half* __restrict__ Whi, const __half* __restrict__ Wlo,
               float* __restrict__ C, int K, int Ntot,
               const float* __restrict__ Dvec, const float* __restrict__ Xres,
               const float* __restrict__ sres_p, float* __restrict__ Xout) {
    extern __shared__ char smem[];
    const uint32_t s0 = smem_u32(smem);
    const int tid  = threadIdx.x;
    const int wid  = tid >> 5;
    const int lane = tid & 31;
    const int wm   = wid & 1;      // M half (64 rows)
    const int wn   = wid >> 1;     // N quarter (32 cols)
    const int bm   = blockIdx.y * 128;
    const int bn   = blockIdx.x * 128;

    float acc[4][4][4];
#pragma unroll
    for (int i = 0; i < 4; i++)
#pragma unroll
        for (int j = 0; j < 4; j++)
#pragma unroll
            for (int q = 0; q < 4; q++) acc[i][j][q] = 0.0f;

    const int NK = K >> 5;   // chunks of 32
    const int frow = tid >> 2;       // 0..63 (A fill row; +64 second)
    const int fq   = tid & 3;        // 0..3

    // prologue: chunk 0 -> buf 0
    fill_w_async<WLO>(Whi, Wlo, bn, K, 0, s0 + 16384, tid);
    cp_commit();
    uint4 pa0 = load_h8(A + (size_t)(bm + frow     )*K + fq*8);
    uint4 pa1 = load_h8(A + (size_t)(bm + frow + 64)*K + fq*8);
    *reinterpret_cast<uint4*>(smem + sw128((uint32_t)(frow*128 + fq*16)))        = pa0;
    *reinterpret_cast<uint4*>(smem + sw128((uint32_t)((frow+64)*128 + fq*16)))   = pa1;
    cp_wait<0>();
    __syncthreads();

    // per-lane ldmatrix address components
    const int a_row = wm*64 + (lane & 7) + ((lane >> 3) & 1)*8;
    const int a_kb  = (lane >> 4) << 4;
    const int b_sub = lane >> 3;
    const int b_row = wn*32 + (lane & 7) + (b_sub >> 1)*8;
    const int b_kb  = (b_sub & 1) << 4;

    for (int t = 0; t < NK; ++t) {
        const int buf = t & 1;
        if (t + 1 < NK) {
            const int k0 = (t + 1) << 5;
            fill_w_async<WLO>(Whi, Wlo, bn, K, k0, s0 + (buf ^ 1)*STAGEB + 16384, tid);
            cp_commit();
            pa0 = load_h8(A + (size_t)(bm + frow     )*K + k0 + fq*8);
            pa1 = load_h8(A + (size_t)(bm + frow + 64)*K + k0 + fq*8);
        }
        const uint32_t As = s0 + buf*STAGEB;
        const uint32_t Ws = As + 16384;
#pragma unroll
        for (int s = 0; s < 2; ++s) {
            uint32_t bh[4][2], bl[4][2];
#pragma unroll
            for (int jj = 0; jj < 2; jj++) {
                uint32_t base = (uint32_t)((b_row + 16*jj)*128 + s*32 + b_kb);
                uint32_t r[4];
                ldsm4(r, Ws + sw128(base));
                bh[2*jj][0] = r[0]; bh[2*jj][1] = r[1];
                bh[2*jj+1][0] = r[2]; bh[2*jj+1][1] = r[3];
                if (WLO) {
                    ldsm4(r, Ws + sw128(base + 64));
                    bl[2*jj][0] = r[0]; bl[2*jj][1] = r[1];
                    bl[2*jj+1][0] = r[2]; bl[2*jj+1][1] = r[3];
                }
            }
#pragma unroll
            for (int i = 0; i < 4; i++) {
                uint32_t ah[4];
                uint32_t base = (uint32_t)((a_row + 16*i)*128 + s*32 + a_kb);
                ldsm4(ah, As + sw128(base));
#pragma unroll
                for (int j = 0; j < 4; j++) {
                    mma_f16(acc[i][j], ah, bh[j]);
                    if (WLO) mma_f16(acc[i][j], ah, bl[j]);
                }
            }
        }
        if (t + 1 < NK) {
            char* s2 = smem + (buf ^ 1)*STAGEB;
            __syncthreads();                 // readers done with buf^1
            *reinterpret_cast<uint4*>(s2 + sw128((uint32_t)(frow*128 + fq*16)))      = pa0;
            *reinterpret_cast<uint4*>(s2 + sw128((uint32_t)((frow+64)*128 + fq*16))) = pa1;
            cp_wait<0>();                    // W(t+1) landed
            __syncthreads();                 // buf^1 ready
        }
    }

    // epilogue
    const int gid = lane >> 2;
    const int tg  = lane & 3;
#pragma unroll
    for (int i = 0; i < 4; i++) {
        const int r0 = bm + wm*64 + i*16 + gid;
#pragma unroll
        for (int j = 0; j < 4; j++) {
            const int col = bn + wn*32 + j*8 + tg*2;
            if (EPI == 2) {
                const float s = *sres_p;
                const int oc = col >> 1;
                float* xp0 = Xout + (size_t)r0 * DM + oc;
                float* xp1 = Xout + (size_t)(r0+8) * DM + oc;
                *xp0 = fmaf(s * acc[i][j][0], 1.0f/(1.0f + expf(-acc[i][j][1])), *xp0);
                *xp1 = fmaf(s * acc[i][j][2], 1.0f/(1.0f + expf(-acc[i][j][3])), *xp1);
            } else {
                if (WGUARD && col >= Ntot) continue;
                float2 v0 = make_float2(acc[i][j][0], acc[i][j][1]);
                float2 v1 = make_float2(acc[i][j][2], acc[i][j][3]);
                if (EPI == 1) {
                    const float2 d  = *reinterpret_cast<const float2*>(Dvec + col);
                    const float2 x0 = *reinterpret_cast<const float2*>(Xres + (size_t)r0*Ntot + col);
                    const float2 x1 = *reinterpret_cast<const float2*>(Xres + (size_t)(r0+8)*Ntot + col);
                    v0.x = fmaf(d.x, x0.x, v0.x); v0.y = fmaf(d.y, x0.y, v0.y);
                    v1.x = fmaf(d.x, x1.x, v1.x); v1.y = fmaf(d.y, x1.y, v1.y);
                }
                *reinterpret_cast<float2*>(C + (size_t)r0*Ntot + col)     = v0;
                *reinterpret_cast<float2*>(C + (size_t)(r0+8)*Ntot + col) = v1;
            }
        }
    }
}

// ---------------- chunked LRU scan ----------------
__global__ void scan_local_kernel(const float* __restrict__ Bu, float* __restrict__ H,
                                  const float* __restrict__ lre_g,
                                  const float* __restrict__ lim_g) {
    int n = threadIdx.x;
    int b = blockIdx.x;
    int c = blockIdx.y;
    float lre = lre_g[n], lim = lim_g[n];
    size_t base = ((size_t)b * LSEQ + (size_t)c * CHLEN) * DM + n;
    float hre = 0.0f, him = 0.0f;
#pragma unroll 4
    for (int t = 0; t < CHLEN; ++t) {
        size_t off = base + (size_t)t * DM;
        float bre = Bu[off];
        float bim = Bu[off + DS];
        float nre = fmaf(lre, hre, fmaf(-lim, him, bre));
        float nim = fmaf(lim, hre, fmaf( lre, him, bim));
        hre = nre; him = nim;
        H[off]      = hre;
        H[off + DS] = him;
    }
    int ci = b * NCH + c;
    g_cend[(size_t)ci*2*DS + n]      = hre;
    g_cend[(size_t)ci*2*DS + DS + n] = him;
}

// carry + fix merged: each (b, c>=1) block rebuilds its carry-in prefix from g_cend
__global__ void scan_fix_kernel(float* __restrict__ H,
                                const float* __restrict__ lre_g,
                                const float* __restrict__ lim_g) {
    int n = threadIdx.x;
    int b = blockIdx.x;
    int c = blockIdx.y + 1;     // chunk 0 needs no fix
    float lre = lre_g[n], lim = lim_g[n];
    // lamP = lam^CHLEN (7 squarings)
    float Pre = lre, Pim = lim;
#pragma unroll
    for (int i = 0; i < 7; i++) {
        float t = Pre*Pre - Pim*Pim;
        Pim = 2.0f*Pre*Pim;
        Pre = t;
    }
    // carry-in for chunk c: s_{j+1} = lamP*s_j + end[j], j = 0..c-1
    float cre = 0.0f, cim = 0.0f;
    for (int j = 0; j < c; ++j) {
        size_t cj = (size_t)(b * NCH + j) * 2 * DS;
        float ere = g_cend[cj + n];
        float eim = g_cend[cj + DS + n];
        float nre = fmaf(Pre, cre, fmaf(-Pim, cim, ere));
        float nim = fmaf(Pim, cre, fmaf( Pre, cim, eim));
        cre = nre; cim = nim;
    }
    float pre = lre, pim = lim;   // lam^(t+1)
    size_t base = ((size_t)b * LSEQ + (size_t)c * CHLEN) * DM + n;
#pragma unroll 4
    for (int t = 0; t < CHLEN; ++t) {
        size_t off = base + (size_t)t * DM;
        float hre = H[off]      + (pre*cre - pim*cim);
        float him = H[off + DS] + (pre*cim + pim*cre);
        H[off]      = hre;
        H[off + DS] = him;
        float npre = pre*lre - pim*lim;
        float npim = pre*lim + pim*lre;
        pre = npre; pim = npim;
    }
}

// ---------------- host launch ----------------
extern "C" void kernel_launch(void* const* d_in, const int* in_sizes, int n_in,
                              void* d_out, int out_size) {
    const float* u      = (const float*)d_in[0];
    const float* enc_w  = (const float*)d_in[1];
    const float* dec_w  = (const float*)d_in[2];
    const float* nu_log = (const float*)d_in[3];
    const float* th_log = (const float*)d_in[4];
    const float* Bre    = (const float*)d_in[5];
    const float* Bim    = (const float*)d_in[6];
    const float* Cre    = (const float*)d_in[7];
    const float* Cim    = (const float*)d_in[8];
    const float* Dv     = (const float*)d_in[9];
    const float* W1     = (const float*)d_in[10];
    const float* W2     = (const float*)d_in[11];
    const float* rlog   = (const float*)d_in[12];
    float* out = (float*)d_out;

    float *px, *pbu, *ph, *pz, *plre, *plim, *psres;
    __half *pWbhi, *pWblo, *pWchi, *pWclo, *pWghi;
    __half *penchi, *penclo, *pdechi, *pdeclo;
    cudaGetSymbolAddress((void**)&px,   g_x);
    cudaGetSymbolAddress((void**)&pbu,  g_bu);
    cudaGetSymbolAddress((void**)&ph,   g_h);
    cudaGetSymbolAddress((void**)&pz,   g_z);
    cudaGetSymbolAddress((void**)&pWbhi, g_Wbhi); cudaGetSymbolAddress((void**)&pWblo, g_Wblo);
    cudaGetSymbolAddress((void**)&pWchi, g_Wchi); cudaGetSymbolAddress((void**)&pWclo, g_Wclo);
    cudaGetSymbolAddress((void**)&pWghi, g_Wghi);
    cudaGetSymbolAddress((void**)&penchi, g_enchi); cudaGetSymbolAddress((void**)&penclo, g_enclo);
    cudaGetSymbolAddress((void**)&pdechi, g_dechi); cudaGetSymbolAddress((void**)&pdeclo, g_declo);
    cudaGetSymbolAddress((void**)&plre,  g_lre);
    cudaGetSymbolAddress((void**)&plim,  g_lim);
    cudaGetSymbolAddress((void**)&psres, g_sres);

    const int SMEM = 2 * STAGEB;   // 64 KB per CTA -> 2 CTAs/SM
    cudaFuncSetAttribute(hmma_gemm<0,false,true>,  cudaFuncAttributeMaxDynamicSharedMemorySize, SMEM);
    cudaFuncSetAttribute(hmma_gemm<1,false,true>,  cudaFuncAttributeMaxDynamicSharedMemorySize, SMEM);
    cudaFuncSetAttribute(hmma_gemm<2,false,false>, cudaFuncAttributeMaxDynamicSharedMemorySize, SMEM);
    cudaFuncSetAttribute(hmma_gemm<0,true,true>,   cudaFuncAttributeMaxDynamicSharedMemorySize, SMEM);

    // prep (4 launches)
    prep_lam_kernel   <<<(NL*DS + 255)/256, 256>>>(nu_log, th_log, rlog);
    prep_wb_enc_kernel<<<(NL*DM*DM + DM*DIN + 255)/256, 256>>>(Bre, Bim, enc_w);
    prep_wc_dec_kernel<<<(NL*DM*DM + 128*DM + 255)/256, 256>>>(Cre, Cim, dec_w);
    prep_wglu_kernel  <<<(NL*2*DM*DM + 255)/256, 256>>>(W1, W2);

    // encoder: x = u @ enc_w^T  (K=64)
    hmma_gemm<0,false,true><<<dim3(DM/128, MTOK/128), 256, SMEM>>>(
        u, penchi, penclo, px, DIN, DM, nullptr, nullptr, nullptr, nullptr);

    for (int l = 0; l < NL; ++l) {
        const float* lre = plre + l*DS;
        const float* lim = plim + l*DS;
        // Bu = x @ Wb^T (gamma folded)
        hmma_gemm<0,false,true><<<dim3(DM/128, MTOK/128), 256, SMEM>>>(
            px, pWbhi + (size_t)l*DM*DM, pWblo + (size_t)l*DM*DM,
            pbu, DM, DM, nullptr, nullptr, nullptr, nullptr);
        scan_local_kernel<<<dim3(NB, NCH), DS>>>(pbu, ph, lre, lim);
        scan_fix_kernel<<<dim3(NB, NCH-1), DS>>>(ph, lre, lim);
        // z = Re(C h) + D*x
        hmma_gemm<1,false,true><<<dim3(DM/128, MTOK/128), 256, SMEM>>>(
            ph, pWchi + (size_t)l*DM*DM, pWclo + (size_t)l*DM*DM,
            pz, DM, DM, Dv + l*DM, px, nullptr, nullptr);
        // GLU GEMM (N=1024 interleaved, single-fp16 W): x += s*g1*sigmoid(g2)
        hmma_gemm<2,false,false><<<dim3(2*DM/128, MTOK/128), 256, SMEM>>>(
            pz, pWghi + (size_t)l*2*DM*DM, nullptr,
            nullptr, DM, 2*DM, nullptr, nullptr, psres + l, px);
    }

    // decoder: out = x @ dec_w^T (N=64 guarded; weights padded to 128 rows)
    hmma_gemm<0,true,true><<<dim3(1, MTOK/128), 256, SMEM>>>(
        px, pdechi, pdeclo, out, DM, DOUT, nullptr, nullptr, nullptr, nullptr);
}

// round 11
// speedup vs baseline: 2.5413x; 1.2988x over previous
#include <cuda_runtime.h>
#include <cuda_fp16.h>
#include <math.h>
#include <string.h>
#include <stdint.h>

#define NB    8
#define LSEQ  2048
#define MTOK  (NB*LSEQ)     // 16384 tokens
#define DIN   64
#define DOUT  64
#define DM    512
#define DS    256
#define NL    4
#define NCH   16
#define CHLEN (LSEQ/NCH)    // 128

// ---------------- scratch (device globals; no allocation allowed) ----------------
__device__ float g_x [MTOK*DM];
__device__ float g_bu[MTOK*DM];           // Bu packed [re(256) | im(256)]
__device__ float g_h [MTOK*DM];           // h  packed [re | im]
__device__ float g_z [MTOK*DM];           // LRU output
// weights: single-fp16 for Bu/C/GLU; hi+lo for encoder/decoder
__device__ __half g_Wb  [NL*DM*DM];
__device__ __half g_Wc  [NL*DM*DM];
__device__ __half g_Wg  [NL*2*DM*DM];
__device__ __half g_enchi[DM*DIN],    g_enclo[DM*DIN];
__device__ __half g_dechi[128*DM],    g_declo[128*DM];   // padded to 128 rows
// scan params / carries
__device__ float g_lre[NL*DS], g_lim[NL*DS], g_gam[NL*DS], g_sres[NL];
__device__ float g_cend[NB*NCH*2*DS];

// ---------------- helpers ----------------
__device__ __forceinline__ uint32_t smem_u32(const void* p) {
    uint32_t a;
    asm("{ .reg .u64 t; cvta.to.shared.u64 t, %1; cvt.u32.u64 %0, t; }" : "=r"(a) : "l"(p));
    return a;
}
__device__ __forceinline__ uint32_t sw128(uint32_t b) { return b ^ ((b >> 3) & 0x70); }

__device__ __forceinline__ void ldsm4(uint32_t* r, uint32_t addr) {
    asm volatile("ldmatrix.sync.aligned.m8n8.x4.shared.b16 {%0,%1,%2,%3}, [%4];"
                 : "=r"(r[0]), "=r"(r[1]), "=r"(r[2]), "=r"(r[3]) : "r"(addr));
}
__device__ __forceinline__ void mma_f16(float* c, const uint32_t* a, const uint32_t* b) {
    asm volatile(
        "mma.sync.aligned.m16n8k16.row.col.f32.f16.f16.f32 "
        "{%0,%1,%2,%3}, {%4,%5,%6,%7}, {%8,%9}, {%0,%1,%2,%3};"
        : "+f"(c[0]), "+f"(c[1]), "+f"(c[2]), "+f"(c[3])
        : "r"(a[0]), "r"(a[1]), "r"(a[2]), "r"(a[3]), "r"(b[0]), "r"(b[1]));
}
__device__ __forceinline__ void cpasync16(uint32_t d, const void* s) {
    asm volatile("cp.async.cg.shared.global [%0], [%1], 16;" :: "r"(d), "l"(s));
}
__device__ __forceinline__ void cp_commit() { asm volatile("cp.async.commit_group;" ::: "memory"); }
template<int N> __device__ __forceinline__ void cp_wait() {
    asm volatile("cp.async.wait_group %0;" :: "n"(N) : "memory");
}

__device__ __forceinline__ uint32_t pkh(float a, float b) {
    __half2 t = __floats2half2_rn(a, b);
    uint32_t u; memcpy(&u, &t, 4); return u;
}

// load 8 fp32 -> 8 fp16 (16B)
__device__ __forceinline__ uint4 load_h8(const float* p) {
    float4 v0 = *reinterpret_cast<const float4*>(p);
    float4 v1 = *reinterpret_cast<const float4*>(p + 4);
    uint4 o;
    o.x = pkh(v0.x, v0.y); o.y = pkh(v0.z, v0.w);
    o.z = pkh(v1.x, v1.y); o.w = pkh(v1.z, v1.w);
    return o;
}

__device__ __forceinline__ void split1h(float v, __half* h, __half* l) {
    __half hh = __float2half_rn(v);
    *h = hh;
    *l = __float2half_rn(v - __half2float(hh));
}

// ---------------- prep kernels (merged) ----------------
__global__ void prep_lam_kernel(const float* __restrict__ nu_log,
                                const float* __restrict__ th_log,
                                const float* __restrict__ rlog) {
    int i = blockIdx.x * blockDim.x + threadIdx.x;
    if (i < NL*DS) {
        float nu = expf(nu_log[i]);
        float r  = expf(-nu);
        float th = expf(th_log[i]);
        g_lre[i] = r * cosf(th);
        g_lim[i] = r * sinf(th);
        g_gam[i] = sqrtf(fmaxf(1.0f - r*r, 0.0f));
    }
    if (i < NL) g_sres[i] = 1.0f / (1.0f + expf(-rlog[i]));
}

__global__ void prep_wb_enc_kernel(const float* __restrict__ Bre, const float* __restrict__ Bim,
                                   const float* __restrict__ enc_w) {
    int idx = blockIdx.x * blockDim.x + threadIdx.x;
    if (idx < NL*DM*DM) {
        int l = idx / (DM*DM), rem = idx - l*(DM*DM);
        int n = rem / DM, k = rem - n*DM;
        float v;
        if (n < DS) v = g_gam[l*DS + n]      * Bre[((size_t)l*DS + n)*DM + k];
        else        v = g_gam[l*DS + n - DS] * Bim[((size_t)l*DS + (n-DS))*DM + k];
        g_Wb[idx] = __float2half_rn(v);
    } else {
        int e = idx - NL*DM*DM;
        if (e < DM*DIN) split1h(enc_w[e], &g_enchi[e], &g_enclo[e]);
    }
}

__global__ void prep_wc_dec_kernel(const float* __restrict__ Cre, const float* __restrict__ Cim,
                                   const float* __restrict__ dec_w) {
    int idx = blockIdx.x * blockDim.x + threadIdx.x;
    if (idx < NL*DM*DM) {
        int l = idx / (DM*DM), rem = idx - l*(DM*DM);
        int d = rem / DM, k = rem - d*DM;
        float v;
        if (k < DS) v =  Cre[((size_t)l*DM + d)*DS + k];
        else        v = -Cim[((size_t)l*DM + d)*DS + (k-DS)];
        g_Wc[idx] = __float2half_rn(v);
    } else {
        int e = idx - NL*DM*DM;
        if (e < 128*DM) {
            int row = e / DM;
            float v = (row < DOUT) ? dec_w[e] : 0.0f;
            split1h(v, &g_dechi[e], &g_declo[e]);
        }
    }
}

__global__ void prep_wglu_kernel(const float* __restrict__ W1, const float* __restrict__ W2) {
    int idx = blockIdx.x * blockDim.x + threadIdx.x;
    if (idx >= NL*2*DM*DM) return;
    int l = idx / (2*DM*DM), rem = idx - l*(2*DM*DM);
    int n = rem / DM, k = rem - n*DM;
    int o = n >> 1;
    float v = (n & 1) ? W2[((size_t)l*DM + o)*DM + k]
                      : W1[((size_t)l*DM + o)*DM + k];
    g_Wg[idx] = __float2half_rn(v);
}

// ---------------- HMMA GEMM ----------------
// A: fp32 -> fp16 inline. W: fp16 hi(+lo if WLO) via cp.async.
// Stage (32KB): A tile 16KB, W tile 16KB (64B hi | 64B lo per row).
// EPI: 0 plain, 1 += Dvec[n]*Xres[m,n], 2 GLU: Xout[m,n/2] += s*even*sigmoid(odd)
#define STAGEB 32768

template<bool WLO>
__device__ __forceinline__ void fill_w_async(const __half* __restrict__ Whi,
                                             const __half* __restrict__ Wlo,
                                             int bn, int K, int k0, uint32_t wdst, int tid) {
    if (WLO) {
        const int wrow  = tid >> 1;     // 0..127
        const int whalf = tid & 1;      // 0 hi, 1 lo
        const char* src = (const char*)((whalf ? Wlo : Whi) + (size_t)(bn + wrow)*K + k0);
        const uint32_t b0 = (uint32_t)(wrow*128 + whalf*64);
#pragma unroll
        for (int q = 0; q < 4; q++)
            cpasync16(wdst + sw128(b0 + q*16), src + q*16);
    } else {
        const int wrow = tid >> 1;      // 0..127
        const int part = tid & 1;       // half of the 64B hi row
        const char* src = (const char*)(Whi + (size_t)(bn + wrow)*K + k0 + part*16);
        const uint32_t b0 = (uint32_t)(wrow*128 + part*32);
#pragma unroll
        for (int q = 0; q < 2; q++)
            cpasync16(wdst + sw128(b0 + q*16), src + q*16);
    }
}

template<int EPI, bool WGUARD, bool WLO>
__global__ __launch_bounds__(256, 2)
void hmma_gemm(const float* __restrict__ A,
               const __half* __restrict__ Whi, const __half* __restrict__ Wlo,
               float* __restrict__ C, int K, int Ntot,
               const float* __restrict__ Dvec, const float* __restrict__ Xres,
               const float* __restrict__ sres_p, float* __restrict__ Xout) {
    extern __shared__ char smem[];
    const uint32_t s0 = smem_u32(smem);
    const int tid  = threadIdx.x;
    const int wid  = tid >> 5;
    const int lane = tid & 31;
    const int wm   = wid & 1;      // M half (64 rows)
    const int wn   = wid >> 1;     // N quarter (32 cols)
    const int bm   = blockIdx.y * 128;
    const int bn   = blockIdx.x * 128;

    float acc[4][4][4];
#pragma unroll
    for (int i = 0; i < 4; i++)
#pragma unroll
        for (int j = 0; j < 4; j++)
#pragma unroll
            for (int q = 0; q < 4; q++) acc[i][j][q] = 0.0f;

    const int NK = K >> 5;   // chunks of 32
    const int frow = tid >> 2;       // 0..63 (A fill row; +64 second)
    const int fq   = tid & 3;        // 0..3

    // prologue: chunk 0 -> buf 0
    fill_w_async<WLO>(Whi, Wlo, bn, K, 0, s0 + 16384, tid);
    cp_commit();
    uint4 pa0 = load_h8(A + (size_t)(bm + frow     )*K + fq*8);
    uint4 pa1 = load_h8(A + (size_t)(bm + frow + 64)*K + fq*8);
    *reinterpret_cast<uint4*>(smem + sw128((uint32_t)(frow*128 + fq*16)))        = pa0;
    *reinterpret_cast<uint4*>(smem + sw128((uint32_t)((frow+64)*128 + fq*16)))   = pa1;
    cp_wait<0>();
    __syncthreads();

    // per-lane ldmatrix address components
    const int a_row = wm*64 + (lane & 7) + ((lane >> 3) & 1)*8;
    const int a_kb  = (lane >> 4) << 4;
    const int b_sub = lane >> 3;
    const int b_row = wn*32 + (lane & 7) + (b_sub >> 1)*8;
    const int b_kb  = (b_sub & 1) << 4;

    for (int t = 0; t < NK; ++t) {
        const int buf = t & 1;
        if (t + 1 < NK) {
            const int k0 = (t + 1) << 5;
            fill_w_async<WLO>(Whi, Wlo, bn, K, k0, s0 + (buf ^ 1)*STAGEB + 16384, tid);
            cp_commit();
            pa0 = load_h8(A + (size_t)(bm + frow     )*K + k0 + fq*8);
            pa1 = load_h8(A + (size_t)(bm + frow + 64)*K + k0 + fq*8);
        }
        const uint32_t As = s0 + buf*STAGEB;
        const uint32_t Ws = As + 16384;
#pragma unroll
        for (int s = 0; s < 2; ++s) {
            uint32_t bh[4][2], bl[4][2];
#pragma unroll
            for (int jj = 0; jj < 2; jj++) {
                uint32_t base = (uint32_t)((b_row + 16*jj)*128 + s*32 + b_kb);
                uint32_t r[4];
                ldsm4(r, Ws + sw128(base));
                bh[2*jj][0] = r[0]; bh[2*jj][1] = r[1];
                bh[2*jj+1][0] = r[2]; bh[2*jj+1][1] = r[3];
                if (WLO) {
                    ldsm4(r, Ws + sw128(base + 64));
                    bl[2*jj][0] = r[0]; bl[2*jj][1] = r[1];
                    bl[2*jj+1][0] = r[2]; bl[2*jj+1][1] = r[3];
                }
            }
#pragma unroll
            for (int i = 0; i < 4; i++) {
                uint32_t ah[4];
                uint32_t base = (uint32_t)((a_row + 16*i)*128 + s*32 + a_kb);
                ldsm4(ah, As + sw128(base));
#pragma unroll
                for (int j = 0; j < 4; j++) {
                    mma_f16(acc[i][j], ah, bh[j]);
                    if (WLO) mma_f16(acc[i][j], ah, bl[j]);
                }
            }
        }
        if (t + 1 < NK) {
            char* s2 = smem + (buf ^ 1)*STAGEB;
            __syncthreads();                 // readers done with buf^1
            *reinterpret_cast<uint4*>(s2 + sw128((uint32_t)(frow*128 + fq*16)))      = pa0;
            *reinterpret_cast<uint4*>(s2 + sw128((uint32_t)((frow+64)*128 + fq*16))) = pa1;
            cp_wait<0>();                    // W(t+1) landed
            __syncthreads();                 // buf^1 ready
        }
    }

    // epilogue
    const int gid = lane >> 2;
    const int tg  = lane & 3;
#pragma unroll
    for (int i = 0; i < 4; i++) {
        const int r0 = bm + wm*64 + i*16 + gid;
#pragma unroll
        for (int j = 0; j < 4; j++) {
            const int col = bn + wn*32 + j*8 + tg*2;
            if (EPI == 2) {
                const float s = *sres_p;
                const int oc = col >> 1;
                float* xp0 = Xout + (size_t)r0 * DM + oc;
                float* xp1 = Xout + (size_t)(r0+8) * DM + oc;
                *xp0 = fmaf(s * acc[i][j][0], 1.0f/(1.0f + expf(-acc[i][j][1])), *xp0);
                *xp1 = fmaf(s * acc[i][j][2], 1.0f/(1.0f + expf(-acc[i][j][3])), *xp1);
            } else {
                if (WGUARD && col >= Ntot) continue;
                float2 v0 = make_float2(acc[i][j][0], acc[i][j][1]);
                float2 v1 = make_float2(acc[i][j][2], acc[i][j][3]);
                if (EPI == 1) {
                    const float2 d  = *reinterpret_cast<const float2*>(Dvec + col);
                    const float2 x0 = *reinterpret_cast<const float2*>(Xres + (size_t)r0*Ntot + col);
                    const float2 x1 = *reinterpret_cast<const float2*>(Xres + (size_t)(r0+8)*Ntot + col);
                    v0.x = fmaf(d.x, x0.x, v0.x); v0.y = fmaf(d.y, x0.y, v0.y);
                    v1.x = fmaf(d.x, x1.x, v1.x); v1.y = fmaf(d.y, x1.y, v1.y);
                }
                *reinterpret_cast<float2*>(C + (size_t)r0*Ntot + col)     = v0;
                *reinterpret_cast<float2*>(C + (size_t)(r0+8)*Ntot + col) = v1;
            }
        }
    }
}

// ---------------- chunked LRU scan ----------------
__global__ void scan_local_kernel(const float* __restrict__ Bu, float* __restrict__ H,
                                  const float* __restrict__ lre_g,
                                  const float* __restrict__ lim_g) {
    int n = threadIdx.x;
    int b = blockIdx.x;
    int c = blockIdx.y;
    float lre = lre_g[n], lim = lim_g[n];
    size_t base = ((size_t)b * LSEQ + (size_t)c * CHLEN) * DM + n;
    float hre = 0.0f, him = 0.0f;
#pragma unroll 4
    for (int t = 0; t < CHLEN; ++t) {
        size_t off = base + (size_t)t * DM;
        float bre = Bu[off];
        float bim = Bu[off + DS];
        float nre = fmaf(lre, hre, fmaf(-lim, him, bre));
        float nim = fmaf(lim, hre, fmaf( lre, him, bim));
        hre = nre; him = nim;
        H[off]      = hre;
        H[off + DS] = him;
    }
    int ci = b * NCH + c;
    g_cend[(size_t)ci*2*DS + n]      = hre;
    g_cend[(size_t)ci*2*DS + DS + n] = him;
}

// carry + fix merged: each (b, c>=1) block rebuilds its carry-in prefix from g_cend
__global__ void scan_fix_kernel(float* __restrict__ H,
                                const float* __restrict__ lre_g,
                                const float* __restrict__ lim_g) {
    int n = threadIdx.x;
    int b = blockIdx.x;
    int c = blockIdx.y + 1;     // chunk 0 needs no fix
    float lre = lre_g[n], lim = lim_g[n];
    // lamP = lam^CHLEN (7 squarings)
    float Pre = lre, Pim = lim;
#pragma unroll
    for (int i = 0; i < 7; i++) {
        float t = Pre*Pre - Pim*Pim;
        Pim = 2.0f*Pre*Pim;
        Pre = t;
    }
    // carry-in for chunk c: s_{j+1} = lamP*s_j + end[j], j = 0..c-1
    float cre = 0.0f, cim = 0.0f;
    for (int j = 0; j < c; ++j) {
        size_t cj = (size_t)(b * NCH + j) * 2 * DS;
        float ere = g_cend[cj + n];
        float eim = g_cend[cj + DS + n];
        float nre = fmaf(Pre, cre, fmaf(-Pim, cim, ere));
        float nim = fmaf(Pim, cre, fmaf( Pre, cim, eim));
        cre = nre; cim = nim;
    }
    float pre = lre, pim = lim;   // lam^(t+1)
    size_t base = ((size_t)b * LSEQ + (size_t)c * CHLEN) * DM + n;
#pragma unroll 4
    for (int t = 0; t < CHLEN; ++t) {
        size_t off = base + (size_t)t * DM;
        float hre = H[off]      + (pre*cre - pim*cim);
        float him = H[off + DS] + (pre*cim + pim*cre);
        H[off]      = hre;
        H[off + DS] = him;
        float npre = pre*lre - pim*lim;
        float npim = pre*lim + pim*lre;
        pre = npre; pim = npim;
    }
}

// ---------------- host launch ----------------
extern "C" void kernel_launch(void* const* d_in, const int* in_sizes, int n_in,
                              void* d_out, int out_size) {
    const float* u      = (const float*)d_in[0];
    const float* enc_w  = (const float*)d_in[1];
    const float* dec_w  = (const float*)d_in[2];
    const float* nu_log = (const float*)d_in[3];
    const float* th_log = (const float*)d_in[4];
    const float* Bre    = (const float*)d_in[5];
    const float* Bim    = (const float*)d_in[6];
    const float* Cre    = (const float*)d_in[7];
    const float* Cim    = (const float*)d_in[8];
    const float* Dv     = (const float*)d_in[9];
    const float* W1     = (const float*)d_in[10];
    const float* W2     = (const float*)d_in[11];
    const float* rlog   = (const float*)d_in[12];
    float* out = (float*)d_out;

    float *px, *pbu, *ph, *pz, *plre, *plim, *psres;
    __half *pWb, *pWc, *pWg;
    __half *penchi, *penclo, *pdechi, *pdeclo;
    cudaGetSymbolAddress((void**)&px,   g_x);
    cudaGetSymbolAddress((void**)&pbu,  g_bu);
    cudaGetSymbolAddress((void**)&ph,   g_h);
    cudaGetSymbolAddress((void**)&pz,   g_z);
    cudaGetSymbolAddress((void**)&pWb,  g_Wb);
    cudaGetSymbolAddress((void**)&pWc,  g_Wc);
    cudaGetSymbolAddress((void**)&pWg,  g_Wg);
    cudaGetSymbolAddress((void**)&penchi, g_enchi); cudaGetSymbolAddress((void**)&penclo, g_enclo);
    cudaGetSymbolAddress((void**)&pdechi, g_dechi); cudaGetSymbolAddress((void**)&pdeclo, g_declo);
    cudaGetSymbolAddress((void**)&plre,  g_lre);
    cudaGetSymbolAddress((void**)&plim,  g_lim);
    cudaGetSymbolAddress((void**)&psres, g_sres);

    const int SMEM = 2 * STAGEB;   // 64 KB per CTA -> 2 CTAs/SM
    cudaFuncSetAttribute(hmma_gemm<0,false,true>,  cudaFuncAttributeMaxDynamicSharedMemorySize, SMEM);
    cudaFuncSetAttribute(hmma_gemm<0,false,false>, cudaFuncAttributeMaxDynamicSharedMemorySize, SMEM);
    cudaFuncSetAttribute(hmma_gemm<1,false,false>, cudaFuncAttributeMaxDynamicSharedMemorySize, SMEM);
    cudaFuncSetAttribute(hmma_gemm<2,false,false>, cudaFuncAttributeMaxDynamicSharedMemorySize, SMEM);
    cudaFuncSetAttribute(hmma_gemm<0,true,true>,   cudaFuncAttributeMaxDynamicSharedMemorySize, SMEM);

    // prep (4 launches)
    prep_lam_kernel   <<<(NL*DS + 255)/256, 256>>>(nu_log, th_log, rlog);
    prep_wb_enc_kernel<<<(NL*DM*DM + DM*DIN + 255)/256, 256>>>(Bre, Bim, enc_w);
    prep_wc_dec_kernel<<<(NL*DM*DM + 128*DM + 255)/256, 256>>>(Cre, Cim, dec_w);
    prep_wglu_kernel  <<<(NL*2*DM*DM + 255)/256, 256>>>(W1, W2);

    // encoder: x = u @ enc_w^T  (K=64, hi+lo)
    hmma_gemm<0,false,true><<<dim3(DM/128, MTOK/128), 256, SMEM>>>(
        u, penchi, penclo, px, DIN, DM, nullptr, nullptr, nullptr, nullptr);

    for (int l = 0; l < NL; ++l) {
        const float* lre = plre + l*DS;
        const float* lim = plim + l*DS;
        // Bu = x @ Wb^T (gamma folded, single-fp16 W)
        hmma_gemm<0,false,false><<<dim3(DM/128, MTOK/128), 256, SMEM>>>(
            px, pWb + (size_t)l*DM*DM, nullptr,
            pbu, DM, DM, nullptr, nullptr, nullptr, nullptr);
        scan_local_kernel<<<dim3(NB, NCH), DS>>>(pbu, ph, lre, lim);
        scan_fix_kernel<<<dim3(NB, NCH-1), DS>>>(ph, lre, lim);
        // z = Re(C h) + D*x (single-fp16 W)
        hmma_gemm<1,false,false><<<dim3(DM/128, MTOK/128), 256, SMEM>>>(
            ph, pWc + (size_t)l*DM*DM, nullptr,
            pz, DM, DM, Dv + l*DM, px, nullptr, nullptr);
        // GLU GEMM (N=1024 interleaved, single-fp16 W): x += s*g1*sigmoid(g2)
        hmma_gemm<2,false,false><<<dim3(2*DM/128, MTOK/128), 256, SMEM>>>(
            pz, pWg + (size_t)l*2*DM*DM, nullptr,
            nullptr, DM, 2*DM, nullptr, nullptr, psres + l, px);
    }

    // decoder: out = x @ dec_w^T (N=64 guarded; hi+lo, padded to 128 rows)
    hmma_gemm<0,true,true><<<dim3(1, MTOK/128), 256, SMEM>>>(
        px, pdechi, pdeclo, out, DM, DOUT, nullptr, nullptr, nullptr, nullptr);
}